// round 2
// baseline (speedup 1.0000x reference)
#include <cuda_runtime.h>
#include <math.h>
#include <stdint.h>

// Problem constants
#define NB   512
#define TT   43
#define NT   (NB*TT)          // 22016 (= 172 * 128)
#define HH   128
#define DKK  96
#define DFF_ 2048
#define OUTV 8000
#define QKVC 576              // 6 * 96 packed [q1 k1 v1 q2 k2 v2]

// ---------------- scratch (device globals; no allocs allowed) ----------------
__device__ float g_xe  [(size_t)NT * HH];      // embedded input
__device__ float g_wqkv[(size_t)QKVC * HH];    // packed qkv weights
__device__ float g_bqkv[QKVC];
__device__ float g_qkv [(size_t)NT * QKVC];    // qkv projections
__device__ float g_hcat[(size_t)NT * 2 * DKK]; // concat head outputs
__device__ float g_mh  [(size_t)NT * HH];
__device__ float g_x1  [(size_t)NT * HH];
__device__ float g_ffh [(size_t)NT * DFF_];    // ffn hidden
__device__ float g_ffo [(size_t)NT * HH];
__device__ float g_x2  [(size_t)NT * HH];

// ---------------- embed: x = emb[inputs] + pos_emb ----------------
__global__ void embed_kernel(const int* __restrict__ inp,
                             const float* __restrict__ emb,
                             const float* __restrict__ pos,
                             float* __restrict__ xe)
{
    int row = blockIdx.x;          // 0..NT-1
    int t   = threadIdx.x;         // 0..127
    int tok = inp[row];
    int tp  = row % TT;
    xe[(size_t)row * HH + t] = emb[(size_t)tok * HH + t] + pos[tp * HH + t];
}

// ---------------- generic SGEMM: C[M,N] = A[M,K] @ W[N,K]^T + bias, opt ReLU --
// BM=BN=128, BK=16, 256 threads, 8x8 register tile per thread.
// M must be a multiple of 128; N guarded; K multiple of 16.
__global__ __launch_bounds__(256) void sgemm_bias(
    const float* __restrict__ A, const float* __restrict__ W,
    const float* __restrict__ bias, float* __restrict__ C,
    int M, int N, int K, int doRelu)
{
    __shared__ float As[16][128];
    __shared__ float Bs[16][128];

    const int t  = threadIdx.x;
    const int m0 = blockIdx.y * 128;
    const int n0 = blockIdx.x * 128;
    const int tm = t >> 4;   // 0..15
    const int tn = t & 15;   // 0..15

    float acc[8][8];
#pragma unroll
    for (int i = 0; i < 8; i++)
#pragma unroll
        for (int j = 0; j < 8; j++) acc[i][j] = 0.f;

    for (int k0 = 0; k0 < K; k0 += 16) {
        // A tile: 128 rows x 16 k, via float4 (512 float4, 2 per thread)
#pragma unroll
        for (int i = 0; i < 2; i++) {
            int idx = t + i * 256;
            int row = idx >> 2;
            int kq  = (idx & 3) * 4;
            float4 v = *reinterpret_cast<const float4*>(
                &A[(size_t)(m0 + row) * K + k0 + kq]);
            As[kq + 0][row] = v.x; As[kq + 1][row] = v.y;
            As[kq + 2][row] = v.z; As[kq + 3][row] = v.w;
        }
        // W tile (rows are output cols), guarded on N
#pragma unroll
        for (int i = 0; i < 2; i++) {
            int idx = t + i * 256;
            int row = idx >> 2;
            int kq  = (idx & 3) * 4;
            float4 v = make_float4(0.f, 0.f, 0.f, 0.f);
            if (n0 + row < N)
                v = *reinterpret_cast<const float4*>(
                    &W[(size_t)(n0 + row) * K + k0 + kq]);
            Bs[kq + 0][row] = v.x; Bs[kq + 1][row] = v.y;
            Bs[kq + 2][row] = v.z; Bs[kq + 3][row] = v.w;
        }
        __syncthreads();

#pragma unroll
        for (int kk = 0; kk < 16; kk++) {
            float a[8], b[8];
            float4 a0 = *reinterpret_cast<const float4*>(&As[kk][tm * 8]);
            float4 a1 = *reinterpret_cast<const float4*>(&As[kk][tm * 8 + 4]);
            float4 b0 = *reinterpret_cast<const float4*>(&Bs[kk][tn * 8]);
            float4 b1 = *reinterpret_cast<const float4*>(&Bs[kk][tn * 8 + 4]);
            a[0]=a0.x; a[1]=a0.y; a[2]=a0.z; a[3]=a0.w;
            a[4]=a1.x; a[5]=a1.y; a[6]=a1.z; a[7]=a1.w;
            b[0]=b0.x; b[1]=b0.y; b[2]=b0.z; b[3]=b0.w;
            b[4]=b1.x; b[5]=b1.y; b[6]=b1.z; b[7]=b1.w;
#pragma unroll
            for (int i = 0; i < 8; i++)
#pragma unroll
                for (int j = 0; j < 8; j++)
                    acc[i][j] = fmaf(a[i], b[j], acc[i][j]);
        }
        __syncthreads();
    }

    // epilogue: bias + optional relu, float4 stores (N % 4 == 0 always here)
#pragma unroll
    for (int i = 0; i < 8; i++) {
        size_t row = (size_t)(m0 + tm * 8 + i);
#pragma unroll
        for (int jq = 0; jq < 2; jq++) {
            int col = n0 + tn * 8 + jq * 4;
            if (col < N) {
                float4 v;
                v.x = acc[i][jq*4+0] + bias[col+0];
                v.y = acc[i][jq*4+1] + bias[col+1];
                v.z = acc[i][jq*4+2] + bias[col+2];
                v.w = acc[i][jq*4+3] + bias[col+3];
                if (doRelu) {
                    v.x = fmaxf(v.x, 0.f); v.y = fmaxf(v.y, 0.f);
                    v.z = fmaxf(v.z, 0.f); v.w = fmaxf(v.w, 0.f);
                }
                *reinterpret_cast<float4*>(&C[row * (size_t)N + col]) = v;
            }
        }
    }
}

// ---------------- attention: one block per (batch, head) ----------------
// dynamic smem: q[43*96] k[43*96] v[43*96] scores[43*43]
__global__ __launch_bounds__(256) void attn_kernel(
    const float* __restrict__ qkv, float* __restrict__ hcat)
{
    extern __shared__ float sm[];
    float* sq = sm;
    float* sk = sq + TT * DKK;
    float* sv = sk + TT * DKK;
    float* ss = sv + TT * DKK;   // 43*43

    const int t  = threadIdx.x;
    const int n  = blockIdx.x >> 1;
    const int hd = blockIdx.x & 1;
    const float scale = 0.10206207261596577f;  // 1/sqrt(96)

    const float* base = qkv + (size_t)n * TT * QKVC + hd * 288;
    for (int idx = t; idx < TT * DKK; idx += 256) {
        int i = idx / DKK, d = idx % DKK;
        const float* r = base + (size_t)i * QKVC;
        sq[idx] = r[d];
        sk[idx] = r[96 + d];
        sv[idx] = r[192 + d];
    }
    __syncthreads();

    // scores
    for (int idx = t; idx < TT * TT; idx += 256) {
        int i = idx / TT, j = idx % TT;
        const float* qi = sq + i * DKK;
        const float* kj = sk + j * DKK;
        float a = 0.f;
#pragma unroll 8
        for (int d = 0; d < DKK; d++) a = fmaf(qi[d], kj[d], a);
        ss[idx] = a * scale;
    }
    __syncthreads();

    // softmax: warp per row (8 warps, rows strided)
    {
        int w = t >> 5, lane = t & 31;
        for (int i = w; i < TT; i += 8) {
            float* row = ss + i * TT;
            float m = -1e30f;
            for (int j = lane; j < TT; j += 32) m = fmaxf(m, row[j]);
#pragma unroll
            for (int o = 16; o; o >>= 1) m = fmaxf(m, __shfl_xor_sync(0xffffffffu, m, o));
            float s = 0.f;
            for (int j = lane; j < TT; j += 32) {
                float e = expf(row[j] - m);
                row[j] = e;
                s += e;
            }
#pragma unroll
            for (int o = 16; o; o >>= 1) s += __shfl_xor_sync(0xffffffffu, s, o);
            float inv = 1.f / s;
            for (int j = lane; j < TT; j += 32) row[j] *= inv;
        }
    }
    __syncthreads();

    // out = attn @ v
    for (int idx = t; idx < TT * DKK; idx += 256) {
        int i = idx / DKK, d = idx % DKK;
        const float* si = ss + i * TT;
        float a = 0.f;
#pragma unroll
        for (int j = 0; j < TT; j++) a = fmaf(si[j], sv[j * DKK + d], a);
        hcat[((size_t)(n * TT + i)) * (2 * DKK) + hd * DKK + d] = a;
    }
}

// ---------------- fused residual-add + LayerNorm (H=128) ----------------
__global__ void add_ln_kernel(const float* __restrict__ a,
                              const float* __restrict__ b,
                              const float* __restrict__ g,
                              const float* __restrict__ be,
                              float* __restrict__ out)
{
    int row = blockIdx.x;
    int t   = threadIdx.x;  // 128
    float v = a[(size_t)row * HH + t] + b[(size_t)row * HH + t];

    __shared__ float red[4];
    float s = v;
#pragma unroll
    for (int o = 16; o; o >>= 1) s += __shfl_xor_sync(0xffffffffu, s, o);
    if ((t & 31) == 0) red[t >> 5] = s;
    __syncthreads();
    float mean = (red[0] + red[1] + red[2] + red[3]) * (1.f / 128.f);
    __syncthreads();

    float d = v - mean;
    float q = d * d;
#pragma unroll
    for (int o = 16; o; o >>= 1) q += __shfl_xor_sync(0xffffffffu, q, o);
    if ((t & 31) == 0) red[t >> 5] = q;
    __syncthreads();
    float var = (red[0] + red[1] + red[2] + red[3]) * (1.f / 128.f);

    out[(size_t)row * HH + t] = d * rsqrtf(var + 1e-5f) * g[t] + be[t];
}

// ---------------- launch ----------------
extern "C" void kernel_launch(void* const* d_in, const int* in_sizes, int n_in,
                              void* d_out, int out_size)
{
    const int*   inp   = (const int*)  d_in[0];
    const float* emb   = (const float*)d_in[1];
    const float* pos   = (const float*)d_in[2];
    const float* Wk1   = (const float*)d_in[3];
    const float* bk1   = (const float*)d_in[4];
    const float* Wv1   = (const float*)d_in[5];
    const float* bv1   = (const float*)d_in[6];
    const float* Wq1   = (const float*)d_in[7];
    const float* bq1   = (const float*)d_in[8];
    const float* Wk2   = (const float*)d_in[9];
    const float* bk2   = (const float*)d_in[10];
    const float* Wv2   = (const float*)d_in[11];
    const float* bv2   = (const float*)d_in[12];
    const float* Wq2   = (const float*)d_in[13];
    const float* bq2   = (const float*)d_in[14];
    const float* Wproj = (const float*)d_in[15];
    const float* bproj = (const float*)d_in[16];
    const float* g_mhp = (const float*)d_in[17];
    const float* b_mhp = (const float*)d_in[18];
    const float* Wff1  = (const float*)d_in[19];
    const float* bff1  = (const float*)d_in[20];
    const float* Wff2  = (const float*)d_in[21];
    const float* bff2  = (const float*)d_in[22];
    const float* g_ffp = (const float*)d_in[23];
    const float* b_ffp = (const float*)d_in[24];
    const float* Wfin  = (const float*)d_in[25];
    const float* bfin  = (const float*)d_in[26];
    float* out = (float*)d_out;

    float *xe, *wqkv, *bqkv, *qkv, *hcat, *mh, *x1, *ffh, *ffo, *x2;
    cudaGetSymbolAddress((void**)&xe,   g_xe);
    cudaGetSymbolAddress((void**)&wqkv, g_wqkv);
    cudaGetSymbolAddress((void**)&bqkv, g_bqkv);
    cudaGetSymbolAddress((void**)&qkv,  g_qkv);
    cudaGetSymbolAddress((void**)&hcat, g_hcat);
    cudaGetSymbolAddress((void**)&mh,   g_mh);
    cudaGetSymbolAddress((void**)&x1,   g_x1);
    cudaGetSymbolAddress((void**)&ffh,  g_ffh);
    cudaGetSymbolAddress((void**)&ffo,  g_ffo);
    cudaGetSymbolAddress((void**)&x2,   g_x2);

    // 1) embed
    embed_kernel<<<NT, 128>>>(inp, emb, pos, xe);

    // 2) pack qkv weights: rows [q1 k1 v1 q2 k2 v2] (96 rows x 128 each)
    const size_t wseg = (size_t)DKK * HH * sizeof(float);
    const size_t bseg = (size_t)DKK * sizeof(float);
    cudaMemcpyAsync(wqkv + 0 * DKK * HH, Wq1, wseg, cudaMemcpyDeviceToDevice);
    cudaMemcpyAsync(wqkv + 1 * DKK * HH, Wk1, wseg, cudaMemcpyDeviceToDevice);
    cudaMemcpyAsync(wqkv + 2 * DKK * HH, Wv1, wseg, cudaMemcpyDeviceToDevice);
    cudaMemcpyAsync(wqkv + 3 * DKK * HH, Wq2, wseg, cudaMemcpyDeviceToDevice);
    cudaMemcpyAsync(wqkv + 4 * DKK * HH, Wk2, wseg, cudaMemcpyDeviceToDevice);
    cudaMemcpyAsync(wqkv + 5 * DKK * HH, Wv2, wseg, cudaMemcpyDeviceToDevice);
    cudaMemcpyAsync(bqkv + 0 * DKK, bq1, bseg, cudaMemcpyDeviceToDevice);
    cudaMemcpyAsync(bqkv + 1 * DKK, bk1, bseg, cudaMemcpyDeviceToDevice);
    cudaMemcpyAsync(bqkv + 2 * DKK, bv1, bseg, cudaMemcpyDeviceToDevice);
    cudaMemcpyAsync(bqkv + 3 * DKK, bq2, bseg, cudaMemcpyDeviceToDevice);
    cudaMemcpyAsync(bqkv + 4 * DKK, bk2, bseg, cudaMemcpyDeviceToDevice);
    cudaMemcpyAsync(bqkv + 5 * DKK, bv2, bseg, cudaMemcpyDeviceToDevice);

    const int MB = NT / 128;  // 172

    // 3) QKV GEMM: [NT,128] x [576,128]^T
    sgemm_bias<<<dim3((QKVC + 127) / 128, MB), 256>>>(
        xe, wqkv, bqkv, qkv, NT, QKVC, HH, 0);

    // 4) attention per (batch, head)
    {
        int smem = (3 * TT * DKK + TT * TT) * (int)sizeof(float); // 56932 B
        cudaFuncSetAttribute(attn_kernel,
                             cudaFuncAttributeMaxDynamicSharedMemorySize, smem);
        attn_kernel<<<NB * 2, 256, smem>>>(qkv, hcat);
    }

    // 5) proj GEMM: [NT,192] x [128,192]^T
    sgemm_bias<<<dim3(1, MB), 256>>>(hcat, Wproj, bproj, mh, NT, HH, 2 * DKK, 0);

    // 6) x1 = LN(mh + xe)
    add_ln_kernel<<<NT, 128>>>(mh, xe, g_mhp, b_mhp, x1);

    // 7) FFN1 + ReLU: [NT,128] x [2048,128]^T
    sgemm_bias<<<dim3(DFF_ / 128, MB), 256>>>(x1, Wff1, bff1, ffh, NT, DFF_, HH, 1);

    // 8) FFN2: [NT,2048] x [128,2048]^T
    sgemm_bias<<<dim3(1, MB), 256>>>(ffh, Wff2, bff2, ffo, NT, HH, DFF_, 0);

    // 9) x2 = LN(ffo + x1)
    add_ln_kernel<<<NT, 128>>>(ffo, x1, g_ffp, b_ffp, x2);

    // 10) final GEMM into d_out: [NT,128] x [8000,128]^T
    sgemm_bias<<<dim3((OUTV + 127) / 128, MB), 256>>>(
        x2, Wfin, bfin, out, NT, OUTV, HH, 0);
}

// round 5
// speedup vs baseline: 2.1883x; 2.1883x over previous
#include <cuda_runtime.h>
#include <cuda_bf16.h>
#include <math.h>
#include <stdint.h>

// Problem constants
#define NB   512
#define TT   43
#define NT   (NB*TT)          // 22016 = 172*128
#define HH   128
#define DKK  96
#define DFF_ 2048
#define OUTV 8000
#define QKVC 576

typedef __nv_bfloat16 bf16;

// ---------------- scratch ----------------
__device__ float g_xe   [(size_t)NT * HH];
__device__ bf16  g_xeh  [(size_t)NT * HH];
__device__ bf16  g_xel  [(size_t)NT * HH];
__device__ bf16  g_wqkvh[(size_t)QKVC * HH];
__device__ bf16  g_wqkvl[(size_t)QKVC * HH];
__device__ float g_bqkv [QKVC];
__device__ float g_qkv  [(size_t)NT * QKVC];
__device__ bf16  g_hcath[(size_t)NT * 192];
__device__ bf16  g_hcatl[(size_t)NT * 192];
__device__ float g_mh   [(size_t)NT * HH];
__device__ float g_x1   [(size_t)NT * HH];
__device__ bf16  g_x1h  [(size_t)NT * HH];
__device__ bf16  g_x1l  [(size_t)NT * HH];
__device__ bf16  g_ffhh [(size_t)NT * DFF_];
__device__ bf16  g_ffhl [(size_t)NT * DFF_];
__device__ float g_ffo  [(size_t)NT * HH];
__device__ bf16  g_x2h  [(size_t)NT * HH];
__device__ bf16  g_x2l  [(size_t)NT * HH];
__device__ bf16  g_wprojh[(size_t)HH * 192];
__device__ bf16  g_wprojl[(size_t)HH * 192];
__device__ bf16  g_wff1h[(size_t)DFF_ * HH];
__device__ bf16  g_wff1l[(size_t)DFF_ * HH];
__device__ bf16  g_wff2h[(size_t)HH * DFF_];
__device__ bf16  g_wff2l[(size_t)HH * DFF_];
__device__ bf16  g_wfinh[(size_t)OUTV * HH];
__device__ bf16  g_wfinl[(size_t)OUTV * HH];

// ---------------- helpers ----------------
__device__ __forceinline__ uint32_t smem_u32(const void* p) {
    uint32_t a;
    asm("{ .reg .u64 t; cvta.to.shared.u64 t, %1; cvt.u32.u64 %0, t; }"
        : "=r"(a) : "l"(p));
    return a;
}
__device__ __forceinline__ void cpa16(uint32_t dst, const void* src, int srcsize) {
    asm volatile("cp.async.ca.shared.global [%0], [%1], 16, %2;"
                 :: "r"(dst), "l"(src), "r"(srcsize) : "memory");
}
__device__ __forceinline__ void cp_commit() {
    asm volatile("cp.async.commit_group;" ::: "memory");
}
__device__ __forceinline__ void cp_wait0() {
    asm volatile("cp.async.wait_group 0;" ::: "memory");
}
__device__ __forceinline__ void cp_wait1() {
    asm volatile("cp.async.wait_group 1;" ::: "memory");
}
__device__ __forceinline__ void ldm4(uint32_t& r0, uint32_t& r1, uint32_t& r2,
                                     uint32_t& r3, uint32_t a) {
    asm volatile("ldmatrix.sync.aligned.m8n8.x4.shared.b16 {%0,%1,%2,%3}, [%4];"
                 : "=r"(r0), "=r"(r1), "=r"(r2), "=r"(r3) : "r"(a));
}
__device__ __forceinline__ void mma16816(float* d, const uint32_t* a,
                                         const uint32_t* b) {
    asm volatile(
        "mma.sync.aligned.m16n8k16.row.col.f32.bf16.bf16.f32 "
        "{%0,%1,%2,%3}, {%4,%5,%6,%7}, {%8,%9}, {%0,%1,%2,%3};"
        : "+f"(d[0]), "+f"(d[1]), "+f"(d[2]), "+f"(d[3])
        : "r"(a[0]), "r"(a[1]), "r"(a[2]), "r"(a[3]), "r"(b[0]), "r"(b[1]));
}
__device__ __forceinline__ void split_store(float v, bf16* h, bf16* l, size_t i) {
    bf16 hi = __float2bfloat16_rn(v);
    h[i] = hi;
    l[i] = __float2bfloat16_rn(v - __bfloat162float(hi));
}

// ================= tensor-core GEMM (mma.sync, bf16 3-pass split) =============
// C[M,N] = (Ah+Al)[M,K] @ (Bh+Bl)[N,K]^T + bias
// 128x128 tile, BK=32, 512 threads, cp.async double-buffered.
// SMEM per stage: Ah,Al,Bh,Bl each 128 rows x 40 bf16 (80B pitch) = 10240 B.
#define LDB  80          // bytes per padded row
#define ASTG 10240       // bytes per array per stage
#define SSTG 40960       // bytes per stage

__global__ __launch_bounds__(512, 1) void tc_gemm(
    const bf16* __restrict__ Ah, const bf16* __restrict__ Al,
    const bf16* __restrict__ Bh, const bf16* __restrict__ Bl,
    const float* __restrict__ bias,
    float* __restrict__ Cf, bf16* __restrict__ Ch, bf16* __restrict__ Cl,
    int N, int K, int relu, int outmode)
{
    extern __shared__ char smem[];
    const uint32_t sbase = smem_u32(smem);
    const int t = threadIdx.x, lane = t & 31;
    const int wid = t >> 5, wm = wid & 3, wn = wid >> 2;
    const int m0 = blockIdx.y * 128, n0 = blockIdx.x * 128;

    // loader mapping: 512 threads -> 128 rows x 4 16B-segments per array
    const int lrow = t >> 2, lseg = t & 3;
    const uint32_t sdst = (uint32_t)(lrow * LDB + lseg * 16);
    const size_t gaoff = (size_t)(m0 + lrow) * K + lseg * 8;
    const int bok = (n0 + lrow < N) ? 16 : 0;
    const size_t gboff = (size_t)(bok ? (n0 + lrow) : n0) * K + lseg * 8;

    float acc[2][4][4];
#pragma unroll
    for (int i = 0; i < 2; i++)
#pragma unroll
        for (int j = 0; j < 4; j++)
#pragma unroll
            for (int k = 0; k < 4; k++) acc[i][j][k] = 0.f;

    const int nc = K >> 5;

    // prefetch chunk 0
    {
        uint32_t sb = sbase;
        cpa16(sb + sdst,             Ah + gaoff, 16);
        cpa16(sb + ASTG + sdst,      Al + gaoff, 16);
        cpa16(sb + 2 * ASTG + sdst,  Bh + gboff, bok);
        cpa16(sb + 3 * ASTG + sdst,  Bl + gboff, bok);
        cp_commit();
    }

    // ldmatrix lane addressing (within-stage byte offsets)
    const uint32_t a_off = (uint32_t)((wm * 32 + (lane & 15)) * LDB
                                      + ((lane >> 4) << 3) * 2);
    const uint32_t b_off = (uint32_t)(2 * ASTG
                                      + (wn * 32 + ((lane >> 4) << 3) + (lane & 7)) * LDB
                                      + (((lane >> 3) & 1) << 3) * 2);

    for (int c = 0; c < nc; c++) {
        if (c + 1 < nc) {
            uint32_t sb = sbase + ((c + 1) & 1) * SSTG;
            size_t ka = (size_t)(c + 1) * 32;
            cpa16(sb + sdst,            Ah + gaoff + ka, 16);
            cpa16(sb + ASTG + sdst,     Al + gaoff + ka, 16);
            cpa16(sb + 2 * ASTG + sdst, Bh + gboff + ka, bok);
            cpa16(sb + 3 * ASTG + sdst, Bl + gboff + ka, bok);
            cp_commit();
            cp_wait1();
        } else {
            cp_wait0();
        }
        __syncthreads();

        const uint32_t sb = sbase + (c & 1) * SSTG;
#pragma unroll
        for (int ks = 0; ks < 2; ks++) {
            const uint32_t kb = ks * 32;   // 16 bf16 = 32 bytes
            uint32_t ah[8], al[8], bh[8], bl[8];
            ldm4(ah[0], ah[1], ah[2], ah[3], sb + a_off + kb);
            ldm4(ah[4], ah[5], ah[6], ah[7], sb + a_off + kb + 16 * LDB);
            ldm4(al[0], al[1], al[2], al[3], sb + ASTG + a_off + kb);
            ldm4(al[4], al[5], al[6], al[7], sb + ASTG + a_off + kb + 16 * LDB);
            ldm4(bh[0], bh[1], bh[2], bh[3], sb + b_off + kb);
            ldm4(bh[4], bh[5], bh[6], bh[7], sb + b_off + kb + 16 * LDB);
            ldm4(bl[0], bl[1], bl[2], bl[3], sb + ASTG + b_off + kb);
            ldm4(bl[4], bl[5], bl[6], bl[7], sb + ASTG + b_off + kb + 16 * LDB);
#pragma unroll
            for (int mt = 0; mt < 2; mt++) {
#pragma unroll
                for (int nt = 0; nt < 4; nt++) {
                    mma16816(acc[mt][nt], ah + mt * 4, bh + nt * 2);
                    mma16816(acc[mt][nt], ah + mt * 4, bl + nt * 2);
                    mma16816(acc[mt][nt], al + mt * 4, bh + nt * 2);
                }
            }
        }
        __syncthreads();
    }

    // epilogue
#pragma unroll
    for (int mt = 0; mt < 2; mt++) {
#pragma unroll
        for (int nt = 0; nt < 4; nt++) {
            int col = n0 + wn * 32 + nt * 8 + (lane & 3) * 2;
            if (col < N) {
                float2 bv = *(const float2*)(bias + col);
                int r0 = m0 + wm * 32 + mt * 16 + (lane >> 2);
                float v0 = acc[mt][nt][0] + bv.x;
                float v1 = acc[mt][nt][1] + bv.y;
                float v2 = acc[mt][nt][2] + bv.x;
                float v3 = acc[mt][nt][3] + bv.y;
                if (relu) {
                    v0 = fmaxf(v0, 0.f); v1 = fmaxf(v1, 0.f);
                    v2 = fmaxf(v2, 0.f); v3 = fmaxf(v3, 0.f);
                }
                if (outmode == 0) {
                    *(float2*)(Cf + (size_t)r0 * N + col)       = make_float2(v0, v1);
                    *(float2*)(Cf + (size_t)(r0 + 8) * N + col) = make_float2(v2, v3);
                } else {
                    bf16 h0 = __float2bfloat16_rn(v0), h1 = __float2bfloat16_rn(v1);
                    bf16 h2 = __float2bfloat16_rn(v2), h3 = __float2bfloat16_rn(v3);
                    bf16 l0 = __float2bfloat16_rn(v0 - __bfloat162float(h0));
                    bf16 l1 = __float2bfloat16_rn(v1 - __bfloat162float(h1));
                    bf16 l2 = __float2bfloat16_rn(v2 - __bfloat162float(h2));
                    bf16 l3 = __float2bfloat16_rn(v3 - __bfloat162float(h3));
                    size_t o0 = (size_t)r0 * N + col, o1 = (size_t)(r0 + 8) * N + col;
                    *(__nv_bfloat162*)(Ch + o0) = __nv_bfloat162(h0, h1);
                    *(__nv_bfloat162*)(Ch + o1) = __nv_bfloat162(h2, h3);
                    *(__nv_bfloat162*)(Cl + o0) = __nv_bfloat162(l0, l1);
                    *(__nv_bfloat162*)(Cl + o1) = __nv_bfloat162(l2, l3);
                }
            }
        }
    }
}

// ---------------- embed + split ----------------
__global__ void embed2_kernel(const int* __restrict__ inp,
                              const float* __restrict__ emb,
                              const float* __restrict__ pos,
                              float* __restrict__ xe,
                              bf16* __restrict__ xh, bf16* __restrict__ xl)
{
    int row = blockIdx.x, t = threadIdx.x;
    int tok = inp[row], tp = row % TT;
    float v = emb[(size_t)tok * HH + t] + pos[tp * HH + t];
    size_t o = (size_t)row * HH + t;
    xe[o] = v;
    split_store(v, xh, xl, o);
}

// ---------------- weight pack/convert ----------------
__global__ void conv_hilo(const float* __restrict__ x, bf16* __restrict__ h,
                          bf16* __restrict__ l, int n)
{
    int i = blockIdx.x * 256 + threadIdx.x;
    if (i < n) split_store(x[i], h, l, i);
}

__global__ void pack_wqkv(const float* q1, const float* k1, const float* v1,
                          const float* q2, const float* k2, const float* v2,
                          bf16* __restrict__ h, bf16* __restrict__ l)
{
    int r = blockIdx.x, c = threadIdx.x;   // 576 x 128
    int seg = r / 96, rr = r % 96;
    const float* src = seg == 0 ? q1 : seg == 1 ? k1 : seg == 2 ? v1
                     : seg == 3 ? q2 : seg == 4 ? k2 : v2;
    split_store(src[rr * 128 + c], h, l, (size_t)r * 128 + c);
}

// ---------------- attention (fp32, hi/lo out) ----------------
__global__ __launch_bounds__(256) void attn_kernel(
    const float* __restrict__ qkv, bf16* __restrict__ hh, bf16* __restrict__ hl)
{
    extern __shared__ float sm[];
    float* sq = sm;
    float* sk = sq + TT * DKK;
    float* sv = sk + TT * DKK;
    float* ss = sv + TT * DKK;

    const int t = threadIdx.x;
    const int n = blockIdx.x >> 1;
    const int hd = blockIdx.x & 1;
    const float scale = 0.10206207261596577f;

    const float* base = qkv + (size_t)n * TT * QKVC + hd * 288;
    for (int idx = t; idx < TT * DKK; idx += 256) {
        int i = idx / DKK, d = idx % DKK;
        const float* r = base + (size_t)i * QKVC;
        sq[idx] = r[d]; sk[idx] = r[96 + d]; sv[idx] = r[192 + d];
    }
    __syncthreads();
    for (int idx = t; idx < TT * TT; idx += 256) {
        int i = idx / TT, j = idx % TT;
        const float* qi = sq + i * DKK;
        const float* kj = sk + j * DKK;
        float a = 0.f;
#pragma unroll 8
        for (int d = 0; d < DKK; d++) a = fmaf(qi[d], kj[d], a);
        ss[idx] = a * scale;
    }
    __syncthreads();
    {
        int w = t >> 5, lane = t & 31;
        for (int i = w; i < TT; i += 8) {
            float* row = ss + i * TT;
            float m = -1e30f;
            for (int j = lane; j < TT; j += 32) m = fmaxf(m, row[j]);
#pragma unroll
            for (int o = 16; o; o >>= 1) m = fmaxf(m, __shfl_xor_sync(~0u, m, o));
            float s = 0.f;
            for (int j = lane; j < TT; j += 32) { float e = expf(row[j] - m); row[j] = e; s += e; }
#pragma unroll
            for (int o = 16; o; o >>= 1) s += __shfl_xor_sync(~0u, s, o);
            float inv = 1.f / s;
            for (int j = lane; j < TT; j += 32) row[j] *= inv;
        }
    }
    __syncthreads();
    for (int idx = t; idx < TT * DKK; idx += 256) {
        int i = idx / DKK, d = idx % DKK;
        const float* si = ss + i * TT;
        float a = 0.f;
#pragma unroll
        for (int j = 0; j < TT; j++) a = fmaf(si[j], sv[j * DKK + d], a);
        size_t o = ((size_t)(n * TT + i)) * 192 + hd * DKK + d;
        split_store(a, hh, hl, o);
    }
}

// ---------------- add + LN + split ----------------
__global__ void add_ln2_kernel(const float* __restrict__ a,
                               const float* __restrict__ b,
                               const float* __restrict__ g,
                               const float* __restrict__ be,
                               float* __restrict__ outf,
                               bf16* __restrict__ oh, bf16* __restrict__ ol)
{
    int row = blockIdx.x, t = threadIdx.x;
    float v = a[(size_t)row * HH + t] + b[(size_t)row * HH + t];
    __shared__ float red[4];
    float s = v;
#pragma unroll
    for (int o = 16; o; o >>= 1) s += __shfl_xor_sync(~0u, s, o);
    if ((t & 31) == 0) red[t >> 5] = s;
    __syncthreads();
    float mean = (red[0] + red[1] + red[2] + red[3]) * (1.f / 128.f);
    __syncthreads();
    float d = v - mean, q = d * d;
#pragma unroll
    for (int o = 16; o; o >>= 1) q += __shfl_xor_sync(~0u, q, o);
    if ((t & 31) == 0) red[t >> 5] = q;
    __syncthreads();
    float var = (red[0] + red[1] + red[2] + red[3]) * (1.f / 128.f);
    float y = d * rsqrtf(var + 1e-5f) * g[t] + be[t];
    size_t o = (size_t)row * HH + t;
    if (outf) outf[o] = y;
    split_store(y, oh, ol, o);
}

// ---------------- launch ----------------
extern "C" void kernel_launch(void* const* d_in, const int* in_sizes, int n_in,
                              void* d_out, int out_size)
{
    const int*   inp   = (const int*)  d_in[0];
    const float* emb   = (const float*)d_in[1];
    const float* pos   = (const float*)d_in[2];
    const float* Wk1   = (const float*)d_in[3];
    const float* bk1   = (const float*)d_in[4];
    const float* Wv1   = (const float*)d_in[5];
    const float* bv1   = (const float*)d_in[6];
    const float* Wq1   = (const float*)d_in[7];
    const float* bq1   = (const float*)d_in[8];
    const float* Wk2   = (const float*)d_in[9];
    const float* bk2   = (const float*)d_in[10];
    const float* Wv2   = (const float*)d_in[11];
    const float* bv2   = (const float*)d_in[12];
    const float* Wq2   = (const float*)d_in[13];
    const float* bq2   = (const float*)d_in[14];
    const float* Wproj = (const float*)d_in[15];
    const float* bproj = (const float*)d_in[16];
    const float* g_mhp = (const float*)d_in[17];
    const float* b_mhp = (const float*)d_in[18];
    const float* Wff1  = (const float*)d_in[19];
    const float* bff1  = (const float*)d_in[20];
    const float* Wff2  = (const float*)d_in[21];
    const float* bff2  = (const float*)d_in[22];
    const float* g_ffp = (const float*)d_in[23];
    const float* b_ffp = (const float*)d_in[24];
    const float* Wfin  = (const float*)d_in[25];
    const float* bfin  = (const float*)d_in[26];
    float* out = (float*)d_out;

    float *xe, *bqkv, *qkv, *mh, *x1, *ffo;
    bf16 *xeh, *xel, *wqh, *wql, *hch, *hcl, *x1h, *x1l, *fhh, *fhl, *x2h, *x2l;
    bf16 *wph, *wpl, *w1h, *w1l, *w2h, *w2l, *wfh, *wfl;
    cudaGetSymbolAddress((void**)&xe,  g_xe);
    cudaGetSymbolAddress((void**)&xeh, g_xeh);
    cudaGetSymbolAddress((void**)&xel, g_xel);
    cudaGetSymbolAddress((void**)&wqh, g_wqkvh);
    cudaGetSymbolAddress((void**)&wql, g_wqkvl);
    cudaGetSymbolAddress((void**)&bqkv, g_bqkv);
    cudaGetSymbolAddress((void**)&qkv, g_qkv);
    cudaGetSymbolAddress((void**)&hch, g_hcath);
    cudaGetSymbolAddress((void**)&hcl, g_hcatl);
    cudaGetSymbolAddress((void**)&mh,  g_mh);
    cudaGetSymbolAddress((void**)&x1,  g_x1);
    cudaGetSymbolAddress((void**)&x1h, g_x1h);
    cudaGetSymbolAddress((void**)&x1l, g_x1l);
    cudaGetSymbolAddress((void**)&fhh, g_ffhh);
    cudaGetSymbolAddress((void**)&fhl, g_ffhl);
    cudaGetSymbolAddress((void**)&ffo, g_ffo);
    cudaGetSymbolAddress((void**)&x2h, g_x2h);
    cudaGetSymbolAddress((void**)&x2l, g_x2l);
    cudaGetSymbolAddress((void**)&wph, g_wprojh);
    cudaGetSymbolAddress((void**)&wpl, g_wprojl);
    cudaGetSymbolAddress((void**)&w1h, g_wff1h);
    cudaGetSymbolAddress((void**)&w1l, g_wff1l);
    cudaGetSymbolAddress((void**)&w2h, g_wff2h);
    cudaGetSymbolAddress((void**)&w2l, g_wff2l);
    cudaGetSymbolAddress((void**)&wfh, g_wfinh);
    cudaGetSymbolAddress((void**)&wfl, g_wfinl);

    const int GSM = 2 * SSTG;   // 81920
    cudaFuncSetAttribute(tc_gemm, cudaFuncAttributeMaxDynamicSharedMemorySize, GSM);
    int asm_ = (3 * TT * DKK + TT * TT) * (int)sizeof(float);
    cudaFuncSetAttribute(attn_kernel, cudaFuncAttributeMaxDynamicSharedMemorySize, asm_);

    // 1) embed + split
    embed2_kernel<<<NT, 128>>>(inp, emb, pos, xe, xeh, xel);

    // 2) weight packing / conversion
    pack_wqkv<<<QKVC, 128>>>(Wq1, Wk1, Wv1, Wq2, Wk2, Wv2, wqh, wql);
    const size_t bseg = (size_t)DKK * sizeof(float);
    cudaMemcpyAsync(bqkv + 0 * DKK, bq1, bseg, cudaMemcpyDeviceToDevice);
    cudaMemcpyAsync(bqkv + 1 * DKK, bk1, bseg, cudaMemcpyDeviceToDevice);
    cudaMemcpyAsync(bqkv + 2 * DKK, bv1, bseg, cudaMemcpyDeviceToDevice);
    cudaMemcpyAsync(bqkv + 3 * DKK, bq2, bseg, cudaMemcpyDeviceToDevice);
    cudaMemcpyAsync(bqkv + 4 * DKK, bk2, bseg, cudaMemcpyDeviceToDevice);
    cudaMemcpyAsync(bqkv + 5 * DKK, bv2, bseg, cudaMemcpyDeviceToDevice);
    conv_hilo<<<(HH * 192 + 255) / 256, 256>>>(Wproj, wph, wpl, HH * 192);
    conv_hilo<<<(DFF_ * HH + 255) / 256, 256>>>(Wff1, w1h, w1l, DFF_ * HH);
    conv_hilo<<<(HH * DFF_ + 255) / 256, 256>>>(Wff2, w2h, w2l, HH * DFF_);
    conv_hilo<<<(OUTV * HH + 255) / 256, 256>>>(Wfin, wfh, wfl, OUTV * HH);

    const int MB = NT / 128;  // 172

    // 3) QKV GEMM [NT,576] fp32 out, K=128
    tc_gemm<<<dim3((QKVC + 127) / 128, MB), 512, GSM>>>(
        xeh, xel, wqh, wql, bqkv, qkv, nullptr, nullptr, QKVC, HH, 0, 0);

    // 4) attention -> hcat hi/lo
    attn_kernel<<<NB * 2, 256, asm_>>>(qkv, hch, hcl);

    // 5) proj GEMM [NT,128], K=192
    tc_gemm<<<dim3(1, MB), 512, GSM>>>(
        hch, hcl, wph, wpl, bproj, mh, nullptr, nullptr, HH, 192, 0, 0);

    // 6) x1 = LN(mh + xe), + split
    add_ln2_kernel<<<NT, 128>>>(mh, xe, g_mhp, b_mhp, x1, x1h, x1l);

    // 7) FFN1 + ReLU -> ffh hi/lo directly, K=128
    tc_gemm<<<dim3(DFF_ / 128, MB), 512, GSM>>>(
        x1h, x1l, w1h, w1l, bff1, nullptr, fhh, fhl, DFF_, HH, 1, 1);

    // 8) FFN2 [NT,128], K=2048
    tc_gemm<<<dim3(1, MB), 512, GSM>>>(
        fhh, fhl, w2h, w2l, bff2, ffo, nullptr, nullptr, HH, DFF_, 0, 0);

    // 9) x2 = LN(ffo + x1), + split
    add_ln2_kernel<<<NT, 128>>>(ffo, x1, g_ffp, b_ffp, nullptr, x2h, x2l);

    // 10) final GEMM [NT,8000] -> d_out, K=128
    tc_gemm<<<dim3((OUTV + 127) / 128, MB), 512, GSM>>>(
        x2h, x2l, wfh, wfl, bfin, out, nullptr, nullptr, OUTV, HH, 0, 0);
}

// round 6
// speedup vs baseline: 2.1926x; 1.0020x over previous
#include <cuda_runtime.h>
#include <cuda_bf16.h>
#include <math.h>
#include <stdint.h>

// Problem constants
#define NB   512
#define TT   43
#define NT   (NB*TT)          // 22016 = 172*128
#define HH   128
#define DKK  96
#define DFF_ 2048
#define OUTV 8000
#define QKVC 576

typedef __nv_bfloat16 bf16;

// ---------------- scratch ----------------
__device__ float g_xe   [(size_t)NT * HH];
__device__ bf16  g_xeh  [(size_t)NT * HH];
__device__ bf16  g_xel  [(size_t)NT * HH];
__device__ bf16  g_wqkvh[(size_t)QKVC * HH];
__device__ bf16  g_wqkvl[(size_t)QKVC * HH];
__device__ float g_bqkv [QKVC];
__device__ float g_qkv  [(size_t)NT * QKVC];
__device__ bf16  g_hcath[(size_t)NT * 192];
__device__ bf16  g_hcatl[(size_t)NT * 192];
__device__ float g_mh   [(size_t)NT * HH];
__device__ float g_x1   [(size_t)NT * HH];
__device__ bf16  g_x1h  [(size_t)NT * HH];
__device__ bf16  g_x1l  [(size_t)NT * HH];
__device__ bf16  g_ffhh [(size_t)NT * DFF_];
__device__ bf16  g_ffhl [(size_t)NT * DFF_];
__device__ float g_ffo  [(size_t)NT * HH];
__device__ bf16  g_x2h  [(size_t)NT * HH];
__device__ bf16  g_x2l  [(size_t)NT * HH];
__device__ bf16  g_wprojh[(size_t)HH * 192];
__device__ bf16  g_wprojl[(size_t)HH * 192];
__device__ bf16  g_wff1h[(size_t)DFF_ * HH];
__device__ bf16  g_wff1l[(size_t)DFF_ * HH];
__device__ bf16  g_wff2h[(size_t)HH * DFF_];
__device__ bf16  g_wff2l[(size_t)HH * DFF_];
__device__ bf16  g_wfinh[(size_t)OUTV * HH];
__device__ bf16  g_wfinl[(size_t)OUTV * HH];

// ---------------- helpers ----------------
__device__ __forceinline__ uint32_t smem_u32(const void* p) {
    uint32_t a;
    asm("{ .reg .u64 t; cvta.to.shared.u64 t, %1; cvt.u32.u64 %0, t; }"
        : "=r"(a) : "l"(p));
    return a;
}
__device__ __forceinline__ void cpa16(uint32_t dst, const void* src, int srcsize) {
    asm volatile("cp.async.ca.shared.global [%0], [%1], 16, %2;"
                 :: "r"(dst), "l"(src), "r"(srcsize) : "memory");
}
__device__ __forceinline__ void cp_commit() {
    asm volatile("cp.async.commit_group;" ::: "memory");
}
__device__ __forceinline__ void cp_wait0() {
    asm volatile("cp.async.wait_group 0;" ::: "memory");
}
__device__ __forceinline__ void cp_wait1() {
    asm volatile("cp.async.wait_group 1;" ::: "memory");
}
__device__ __forceinline__ void ldm4(uint32_t& r0, uint32_t& r1, uint32_t& r2,
                                     uint32_t& r3, uint32_t a) {
    asm volatile("ldmatrix.sync.aligned.m8n8.x4.shared.b16 {%0,%1,%2,%3}, [%4];"
                 : "=r"(r0), "=r"(r1), "=r"(r2), "=r"(r3) : "r"(a));
}
__device__ __forceinline__ void mma16816(float* d, const uint32_t* a,
                                         const uint32_t* b) {
    asm volatile(
        "mma.sync.aligned.m16n8k16.row.col.f32.bf16.bf16.f32 "
        "{%0,%1,%2,%3}, {%4,%5,%6,%7}, {%8,%9}, {%0,%1,%2,%3};"
        : "+f"(d[0]), "+f"(d[1]), "+f"(d[2]), "+f"(d[3])
        : "r"(a[0]), "r"(a[1]), "r"(a[2]), "r"(a[3]), "r"(b[0]), "r"(b[1]));
}
__device__ __forceinline__ void split_store(float v, bf16* h, bf16* l, size_t i) {
    bf16 hi = __float2bfloat16_rn(v);
    h[i] = hi;
    l[i] = __float2bfloat16_rn(v - __bfloat162float(hi));
}

// ================= tensor-core GEMM (mma.sync, bf16 3-pass split) =============
// C[M,N] = (Ah+Al)[M,K] @ (Bh+Bl)[N,K]^T + bias
// 128x128 tile, BK=32, 512 threads, cp.async double-buffered.
// SMEM per stage: Ah,Al,Bh,Bl each 128 rows x 40 bf16 (80B pitch) = 10240 B.
#define LDB  80          // bytes per padded row
#define ASTG 10240       // bytes per array per stage
#define SSTG 40960       // bytes per stage

__global__ __launch_bounds__(512, 1) void tc_gemm(
    const bf16* __restrict__ Ah, const bf16* __restrict__ Al,
    const bf16* __restrict__ Bh, const bf16* __restrict__ Bl,
    const float* __restrict__ bias,
    float* __restrict__ Cf, bf16* __restrict__ Ch, bf16* __restrict__ Cl,
    int N, int K, int relu, int outmode)
{
    extern __shared__ char smem[];
    const uint32_t sbase = smem_u32(smem);
    const int t = threadIdx.x, lane = t & 31;
    const int wid = t >> 5, wm = wid & 3, wn = wid >> 2;
    const int m0 = blockIdx.y * 128, n0 = blockIdx.x * 128;

    // loader mapping: 512 threads -> 128 rows x 4 16B-segments per array
    const int lrow = t >> 2, lseg = t & 3;
    const uint32_t sdst = (uint32_t)(lrow * LDB + lseg * 16);
    const size_t gaoff = (size_t)(m0 + lrow) * K + lseg * 8;
    const int bok = (n0 + lrow < N) ? 16 : 0;
    const size_t gboff = (size_t)(bok ? (n0 + lrow) : n0) * K + lseg * 8;

    float acc[2][4][4];
#pragma unroll
    for (int i = 0; i < 2; i++)
#pragma unroll
        for (int j = 0; j < 4; j++)
#pragma unroll
            for (int k = 0; k < 4; k++) acc[i][j][k] = 0.f;

    const int nc = K >> 5;

    // prefetch chunk 0
    {
        uint32_t sb = sbase;
        cpa16(sb + sdst,             Ah + gaoff, 16);
        cpa16(sb + ASTG + sdst,      Al + gaoff, 16);
        cpa16(sb + 2 * ASTG + sdst,  Bh + gboff, bok);
        cpa16(sb + 3 * ASTG + sdst,  Bl + gboff, bok);
        cp_commit();
    }

    // ldmatrix lane addressing (within-stage byte offsets)
    const uint32_t a_off = (uint32_t)((wm * 32 + (lane & 15)) * LDB
                                      + ((lane >> 4) << 3) * 2);
    const uint32_t b_off = (uint32_t)(2 * ASTG
                                      + (wn * 32 + ((lane >> 4) << 3) + (lane & 7)) * LDB
                                      + (((lane >> 3) & 1) << 3) * 2);

    for (int c = 0; c < nc; c++) {
        if (c + 1 < nc) {
            uint32_t sb = sbase + ((c + 1) & 1) * SSTG;
            size_t ka = (size_t)(c + 1) * 32;
            cpa16(sb + sdst,            Ah + gaoff + ka, 16);
            cpa16(sb + ASTG + sdst,     Al + gaoff + ka, 16);
            cpa16(sb + 2 * ASTG + sdst, Bh + gboff + ka, bok);
            cpa16(sb + 3 * ASTG + sdst, Bl + gboff + ka, bok);
            cp_commit();
            cp_wait1();
        } else {
            cp_wait0();
        }
        __syncthreads();

        const uint32_t sb = sbase + (c & 1) * SSTG;
#pragma unroll
        for (int ks = 0; ks < 2; ks++) {
            const uint32_t kb = ks * 32;   // 16 bf16 = 32 bytes
            uint32_t ah[8], al[8], bh[8], bl[8];
            ldm4(ah[0], ah[1], ah[2], ah[3], sb + a_off + kb);
            ldm4(ah[4], ah[5], ah[6], ah[7], sb + a_off + kb + 16 * LDB);
            ldm4(al[0], al[1], al[2], al[3], sb + ASTG + a_off + kb);
            ldm4(al[4], al[5], al[6], al[7], sb + ASTG + a_off + kb + 16 * LDB);
            ldm4(bh[0], bh[1], bh[2], bh[3], sb + b_off + kb);
            ldm4(bh[4], bh[5], bh[6], bh[7], sb + b_off + kb + 16 * LDB);
            ldm4(bl[0], bl[1], bl[2], bl[3], sb + ASTG + b_off + kb);
            ldm4(bl[4], bl[5], bl[6], bl[7], sb + ASTG + b_off + kb + 16 * LDB);
#pragma unroll
            for (int mt = 0; mt < 2; mt++) {
#pragma unroll
                for (int nt = 0; nt < 4; nt++) {
                    mma16816(acc[mt][nt], ah + mt * 4, bh + nt * 2);
                    mma16816(acc[mt][nt], ah + mt * 4, bl + nt * 2);
                    mma16816(acc[mt][nt], al + mt * 4, bh + nt * 2);
                }
            }
        }
        __syncthreads();
    }

    // epilogue
#pragma unroll
    for (int mt = 0; mt < 2; mt++) {
#pragma unroll
        for (int nt = 0; nt < 4; nt++) {
            int col = n0 + wn * 32 + nt * 8 + (lane & 3) * 2;
            if (col < N) {
                float2 bv = *(const float2*)(bias + col);
                int r0 = m0 + wm * 32 + mt * 16 + (lane >> 2);
                float v0 = acc[mt][nt][0] + bv.x;
                float v1 = acc[mt][nt][1] + bv.y;
                float v2 = acc[mt][nt][2] + bv.x;
                float v3 = acc[mt][nt][3] + bv.y;
                if (relu) {
                    v0 = fmaxf(v0, 0.f); v1 = fmaxf(v1, 0.f);
                    v2 = fmaxf(v2, 0.f); v3 = fmaxf(v3, 0.f);
                }
                if (outmode == 0) {
                    *(float2*)(Cf + (size_t)r0 * N + col)       = make_float2(v0, v1);
                    *(float2*)(Cf + (size_t)(r0 + 8) * N + col) = make_float2(v2, v3);
                } else {
                    bf16 h0 = __float2bfloat16_rn(v0), h1 = __float2bfloat16_rn(v1);
                    bf16 h2 = __float2bfloat16_rn(v2), h3 = __float2bfloat16_rn(v3);
                    bf16 l0 = __float2bfloat16_rn(v0 - __bfloat162float(h0));
                    bf16 l1 = __float2bfloat16_rn(v1 - __bfloat162float(h1));
                    bf16 l2 = __float2bfloat16_rn(v2 - __bfloat162float(h2));
                    bf16 l3 = __float2bfloat16_rn(v3 - __bfloat162float(h3));
                    size_t o0 = (size_t)r0 * N + col, o1 = (size_t)(r0 + 8) * N + col;
                    *(__nv_bfloat162*)(Ch + o0) = __nv_bfloat162(h0, h1);
                    *(__nv_bfloat162*)(Ch + o1) = __nv_bfloat162(h2, h3);
                    *(__nv_bfloat162*)(Cl + o0) = __nv_bfloat162(l0, l1);
                    *(__nv_bfloat162*)(Cl + o1) = __nv_bfloat162(l2, l3);
                }
            }
        }
    }
}

// ---------------- embed + split ----------------
__global__ void embed2_kernel(const int* __restrict__ inp,
                              const float* __restrict__ emb,
                              const float* __restrict__ pos,
                              float* __restrict__ xe,
                              bf16* __restrict__ xh, bf16* __restrict__ xl)
{
    int row = blockIdx.x, t = threadIdx.x;
    int tok = inp[row], tp = row % TT;
    float v = emb[(size_t)tok * HH + t] + pos[tp * HH + t];
    size_t o = (size_t)row * HH + t;
    xe[o] = v;
    split_store(v, xh, xl, o);
}

// ---------------- weight pack/convert ----------------
__global__ void conv_hilo(const float* __restrict__ x, bf16* __restrict__ h,
                          bf16* __restrict__ l, int n)
{
    int i = blockIdx.x * 256 + threadIdx.x;
    if (i < n) split_store(x[i], h, l, i);
}

__global__ void pack_wqkv(const float* q1, const float* k1, const float* v1,
                          const float* q2, const float* k2, const float* v2,
                          bf16* __restrict__ h, bf16* __restrict__ l)
{
    int r = blockIdx.x, c = threadIdx.x;   // 576 x 128
    int seg = r / 96, rr = r % 96;
    const float* src = seg == 0 ? q1 : seg == 1 ? k1 : seg == 2 ? v1
                     : seg == 3 ? q2 : seg == 4 ? k2 : v2;
    split_store(src[rr * 128 + c], h, l, (size_t)r * 128 + c);
}

// ---------------- attention (fp32, hi/lo out) ----------------
__global__ __launch_bounds__(256) void attn_kernel(
    const float* __restrict__ qkv, bf16* __restrict__ hh, bf16* __restrict__ hl)
{
    extern __shared__ float sm[];
    float* sq = sm;
    float* sk = sq + TT * DKK;
    float* sv = sk + TT * DKK;
    float* ss = sv + TT * DKK;

    const int t = threadIdx.x;
    const int n = blockIdx.x >> 1;
    const int hd = blockIdx.x & 1;
    const float scale = 0.10206207261596577f;

    const float* base = qkv + (size_t)n * TT * QKVC + hd * 288;
    for (int idx = t; idx < TT * DKK; idx += 256) {
        int i = idx / DKK, d = idx % DKK;
        const float* r = base + (size_t)i * QKVC;
        sq[idx] = r[d]; sk[idx] = r[96 + d]; sv[idx] = r[192 + d];
    }
    __syncthreads();
    for (int idx = t; idx < TT * TT; idx += 256) {
        int i = idx / TT, j = idx % TT;
        const float* qi = sq + i * DKK;
        const float* kj = sk + j * DKK;
        float a = 0.f;
#pragma unroll 8
        for (int d = 0; d < DKK; d++) a = fmaf(qi[d], kj[d], a);
        ss[idx] = a * scale;
    }
    __syncthreads();
    {
        int w = t >> 5, lane = t & 31;
        for (int i = w; i < TT; i += 8) {
            float* row = ss + i * TT;
            float m = -1e30f;
            for (int j = lane; j < TT; j += 32) m = fmaxf(m, row[j]);
#pragma unroll
            for (int o = 16; o; o >>= 1) m = fmaxf(m, __shfl_xor_sync(~0u, m, o));
            float s = 0.f;
            for (int j = lane; j < TT; j += 32) { float e = expf(row[j] - m); row[j] = e; s += e; }
#pragma unroll
            for (int o = 16; o; o >>= 1) s += __shfl_xor_sync(~0u, s, o);
            float inv = 1.f / s;
            for (int j = lane; j < TT; j += 32) row[j] *= inv;
        }
    }
    __syncthreads();
    for (int idx = t; idx < TT * DKK; idx += 256) {
        int i = idx / DKK, d = idx % DKK;
        const float* si = ss + i * TT;
        float a = 0.f;
#pragma unroll
        for (int j = 0; j < TT; j++) a = fmaf(si[j], sv[j * DKK + d], a);
        size_t o = ((size_t)(n * TT + i)) * 192 + hd * DKK + d;
        split_store(a, hh, hl, o);
    }
}

// ---------------- add + LN + split ----------------
__global__ void add_ln2_kernel(const float* __restrict__ a,
                               const float* __restrict__ b,
                               const float* __restrict__ g,
                               const float* __restrict__ be,
                               float* __restrict__ outf,
                               bf16* __restrict__ oh, bf16* __restrict__ ol)
{
    int row = blockIdx.x, t = threadIdx.x;
    float v = a[(size_t)row * HH + t] + b[(size_t)row * HH + t];
    __shared__ float red[4];
    float s = v;
#pragma unroll
    for (int o = 16; o; o >>= 1) s += __shfl_xor_sync(~0u, s, o);
    if ((t & 31) == 0) red[t >> 5] = s;
    __syncthreads();
    float mean = (red[0] + red[1] + red[2] + red[3]) * (1.f / 128.f);
    __syncthreads();
    float d = v - mean, q = d * d;
#pragma unroll
    for (int o = 16; o; o >>= 1) q += __shfl_xor_sync(~0u, q, o);
    if ((t & 31) == 0) red[t >> 5] = q;
    __syncthreads();
    float var = (red[0] + red[1] + red[2] + red[3]) * (1.f / 128.f);
    float y = d * rsqrtf(var + 1e-5f) * g[t] + be[t];
    size_t o = (size_t)row * HH + t;
    if (outf) outf[o] = y;
    split_store(y, oh, ol, o);
}

// ---------------- launch ----------------
extern "C" void kernel_launch(void* const* d_in, const int* in_sizes, int n_in,
                              void* d_out, int out_size)
{
    const int*   inp   = (const int*)  d_in[0];
    const float* emb   = (const float*)d_in[1];
    const float* pos   = (const float*)d_in[2];
    const float* Wk1   = (const float*)d_in[3];
    const float* bk1   = (const float*)d_in[4];
    const float* Wv1   = (const float*)d_in[5];
    const float* bv1   = (const float*)d_in[6];
    const float* Wq1   = (const float*)d_in[7];
    const float* bq1   = (const float*)d_in[8];
    const float* Wk2   = (const float*)d_in[9];
    const float* bk2   = (const float*)d_in[10];
    const float* Wv2   = (const float*)d_in[11];
    const float* bv2   = (const float*)d_in[12];
    const float* Wq2   = (const float*)d_in[13];
    const float* bq2   = (const float*)d_in[14];
    const float* Wproj = (const float*)d_in[15];
    const float* bproj = (const float*)d_in[16];
    const float* g_mhp = (const float*)d_in[17];
    const float* b_mhp = (const float*)d_in[18];
    const float* Wff1  = (const float*)d_in[19];
    const float* bff1  = (const float*)d_in[20];
    const float* Wff2  = (const float*)d_in[21];
    const float* bff2  = (const float*)d_in[22];
    const float* g_ffp = (const float*)d_in[23];
    const float* b_ffp = (const float*)d_in[24];
    const float* Wfin  = (const float*)d_in[25];
    const float* bfin  = (const float*)d_in[26];
    float* out = (float*)d_out;

    float *xe, *bqkv, *qkv, *mh, *x1, *ffo;
    bf16 *xeh, *xel, *wqh, *wql, *hch, *hcl, *x1h, *x1l, *fhh, *fhl, *x2h, *x2l;
    bf16 *wph, *wpl, *w1h, *w1l, *w2h, *w2l, *wfh, *wfl;
    cudaGetSymbolAddress((void**)&xe,  g_xe);
    cudaGetSymbolAddress((void**)&xeh, g_xeh);
    cudaGetSymbolAddress((void**)&xel, g_xel);
    cudaGetSymbolAddress((void**)&wqh, g_wqkvh);
    cudaGetSymbolAddress((void**)&wql, g_wqkvl);
    cudaGetSymbolAddress((void**)&bqkv, g_bqkv);
    cudaGetSymbolAddress((void**)&qkv, g_qkv);
    cudaGetSymbolAddress((void**)&hch, g_hcath);
    cudaGetSymbolAddress((void**)&hcl, g_hcatl);
    cudaGetSymbolAddress((void**)&mh,  g_mh);
    cudaGetSymbolAddress((void**)&x1,  g_x1);
    cudaGetSymbolAddress((void**)&x1h, g_x1h);
    cudaGetSymbolAddress((void**)&x1l, g_x1l);
    cudaGetSymbolAddress((void**)&fhh, g_ffhh);
    cudaGetSymbolAddress((void**)&fhl, g_ffhl);
    cudaGetSymbolAddress((void**)&ffo, g_ffo);
    cudaGetSymbolAddress((void**)&x2h, g_x2h);
    cudaGetSymbolAddress((void**)&x2l, g_x2l);
    cudaGetSymbolAddress((void**)&wph, g_wprojh);
    cudaGetSymbolAddress((void**)&wpl, g_wprojl);
    cudaGetSymbolAddress((void**)&w1h, g_wff1h);
    cudaGetSymbolAddress((void**)&w1l, g_wff1l);
    cudaGetSymbolAddress((void**)&w2h, g_wff2h);
    cudaGetSymbolAddress((void**)&w2l, g_wff2l);
    cudaGetSymbolAddress((void**)&wfh, g_wfinh);
    cudaGetSymbolAddress((void**)&wfl, g_wfinl);

    const int GSM = 2 * SSTG;   // 81920
    cudaFuncSetAttribute(tc_gemm, cudaFuncAttributeMaxDynamicSharedMemorySize, GSM);
    int asm_ = (3 * TT * DKK + TT * TT) * (int)sizeof(float);
    cudaFuncSetAttribute(attn_kernel, cudaFuncAttributeMaxDynamicSharedMemorySize, asm_);

    // 1) embed + split
    embed2_kernel<<<NT, 128>>>(inp, emb, pos, xe, xeh, xel);

    // 2) weight packing / conversion
    pack_wqkv<<<QKVC, 128>>>(Wq1, Wk1, Wv1, Wq2, Wk2, Wv2, wqh, wql);
    const size_t bseg = (size_t)DKK * sizeof(float);
    cudaMemcpyAsync(bqkv + 0 * DKK, bq1, bseg, cudaMemcpyDeviceToDevice);
    cudaMemcpyAsync(bqkv + 1 * DKK, bk1, bseg, cudaMemcpyDeviceToDevice);
    cudaMemcpyAsync(bqkv + 2 * DKK, bv1, bseg, cudaMemcpyDeviceToDevice);
    cudaMemcpyAsync(bqkv + 3 * DKK, bq2, bseg, cudaMemcpyDeviceToDevice);
    cudaMemcpyAsync(bqkv + 4 * DKK, bk2, bseg, cudaMemcpyDeviceToDevice);
    cudaMemcpyAsync(bqkv + 5 * DKK, bv2, bseg, cudaMemcpyDeviceToDevice);
    conv_hilo<<<(HH * 192 + 255) / 256, 256>>>(Wproj, wph, wpl, HH * 192);
    conv_hilo<<<(DFF_ * HH + 255) / 256, 256>>>(Wff1, w1h, w1l, DFF_ * HH);
    conv_hilo<<<(HH * DFF_ + 255) / 256, 256>>>(Wff2, w2h, w2l, HH * DFF_);
    conv_hilo<<<(OUTV * HH + 255) / 256, 256>>>(Wfin, wfh, wfl, OUTV * HH);

    const int MB = NT / 128;  // 172

    // 3) QKV GEMM [NT,576] fp32 out, K=128
    tc_gemm<<<dim3((QKVC + 127) / 128, MB), 512, GSM>>>(
        xeh, xel, wqh, wql, bqkv, qkv, nullptr, nullptr, QKVC, HH, 0, 0);

    // 4) attention -> hcat hi/lo
    attn_kernel<<<NB * 2, 256, asm_>>>(qkv, hch, hcl);

    // 5) proj GEMM [NT,128], K=192
    tc_gemm<<<dim3(1, MB), 512, GSM>>>(
        hch, hcl, wph, wpl, bproj, mh, nullptr, nullptr, HH, 192, 0, 0);

    // 6) x1 = LN(mh + xe), + split
    add_ln2_kernel<<<NT, 128>>>(mh, xe, g_mhp, b_mhp, x1, x1h, x1l);

    // 7) FFN1 + ReLU -> ffh hi/lo directly, K=128
    tc_gemm<<<dim3(DFF_ / 128, MB), 512, GSM>>>(
        x1h, x1l, w1h, w1l, bff1, nullptr, fhh, fhl, DFF_, HH, 1, 1);

    // 8) FFN2 [NT,128], K=2048
    tc_gemm<<<dim3(1, MB), 512, GSM>>>(
        fhh, fhl, w2h, w2l, bff2, ffo, nullptr, nullptr, HH, DFF_, 0, 0);

    // 9) x2 = LN(ffo + x1), + split
    add_ln2_kernel<<<NT, 128>>>(ffo, x1, g_ffp, b_ffp, nullptr, x2h, x2l);

    // 10) final GEMM [NT,8000] -> d_out, K=128
    tc_gemm<<<dim3((OUTV + 127) / 128, MB), 512, GSM>>>(
        x2h, x2l, wfh, wfl, bfin, out, nullptr, nullptr, OUTV, HH, 0, 0);
}

// round 7
// speedup vs baseline: 2.6361x; 1.2023x over previous
#include <cuda_runtime.h>
#include <cuda_fp16.h>
#include <math.h>
#include <stdint.h>

// Problem constants
#define NB   512
#define TT   43
#define NT   (NB*TT)          // 22016 = 172*128
#define HH   128
#define DKK  96
#define DFF_ 2048
#define OUTV 8000
#define QKVC 576

typedef __half fp16;

// ---------------- scratch ----------------
__device__ float g_xe   [(size_t)NT * HH];
__device__ fp16  g_xeh  [(size_t)NT * HH];
__device__ fp16  g_wqkvh[(size_t)QKVC * HH];
__device__ fp16  g_wqkvl[(size_t)QKVC * HH];
__device__ float g_bqkv [QKVC];
__device__ fp16  g_qkv  [(size_t)NT * QKVC];
__device__ fp16  g_hcat [(size_t)NT * 192];
__device__ float g_mh   [(size_t)NT * HH];
__device__ float g_x1   [(size_t)NT * HH];
__device__ fp16  g_x1h  [(size_t)NT * HH];
__device__ fp16  g_ffh  [(size_t)NT * DFF_];
__device__ float g_ffo  [(size_t)NT * HH];
__device__ fp16  g_x2h  [(size_t)NT * HH];
__device__ fp16  g_wprojh[(size_t)HH * 192];
__device__ fp16  g_wprojl[(size_t)HH * 192];
__device__ fp16  g_wff1h[(size_t)DFF_ * HH];
__device__ fp16  g_wff1l[(size_t)DFF_ * HH];
__device__ fp16  g_wff2h[(size_t)HH * DFF_];
__device__ fp16  g_wff2l[(size_t)HH * DFF_];
__device__ fp16  g_wfinh[(size_t)OUTV * HH];
__device__ fp16  g_wfinl[(size_t)OUTV * HH];

// ---------------- helpers ----------------
__device__ __forceinline__ uint32_t smem_u32(const void* p) {
    uint32_t a;
    asm("{ .reg .u64 t; cvta.to.shared.u64 t, %1; cvt.u32.u64 %0, t; }"
        : "=r"(a) : "l"(p));
    return a;
}
__device__ __forceinline__ void cpa16(uint32_t dst, const void* src, int srcsize) {
    asm volatile("cp.async.ca.shared.global [%0], [%1], 16, %2;"
                 :: "r"(dst), "l"(src), "r"(srcsize) : "memory");
}
__device__ __forceinline__ void cp_commit() {
    asm volatile("cp.async.commit_group;" ::: "memory");
}
__device__ __forceinline__ void cp_wait0() {
    asm volatile("cp.async.wait_group 0;" ::: "memory");
}
__device__ __forceinline__ void cp_wait1() {
    asm volatile("cp.async.wait_group 1;" ::: "memory");
}
__device__ __forceinline__ void ldm4(uint32_t& r0, uint32_t& r1, uint32_t& r2,
                                     uint32_t& r3, uint32_t a) {
    asm volatile("ldmatrix.sync.aligned.m8n8.x4.shared.b16 {%0,%1,%2,%3}, [%4];"
                 : "=r"(r0), "=r"(r1), "=r"(r2), "=r"(r3) : "r"(a));
}
__device__ __forceinline__ void mma16816(float* d, const uint32_t* a,
                                         const uint32_t* b) {
    asm volatile(
        "mma.sync.aligned.m16n8k16.row.col.f32.f16.f16.f32 "
        "{%0,%1,%2,%3}, {%4,%5,%6,%7}, {%8,%9}, {%0,%1,%2,%3};"
        : "+f"(d[0]), "+f"(d[1]), "+f"(d[2]), "+f"(d[3])
        : "r"(a[0]), "r"(a[1]), "r"(a[2]), "r"(a[3]), "r"(b[0]), "r"(b[1]));
}
__device__ __forceinline__ void split_store_h(float v, fp16* h, fp16* l, size_t i) {
    fp16 hi = __float2half_rn(v);
    h[i] = hi;
    l[i] = __float2half_rn(v - __half2float(hi));
}

// ================= tensor-core GEMM (mma.sync fp16, 2-pass weight split) ======
// C[M,N] = A[M,K](fp16) @ (Bh+Bl)[N,K]^T + bias
// 128x128 tile, BK=32, 512 threads, 3-stage cp.async pipeline.
// SMEM per stage: A, Bh, Bl each 128 rows x 80B pitch = 10240 B.
#define LDB  80
#define ASTG 10240
#define SSTG (3*ASTG)        // 30720 per stage
#define NSTG 3

__global__ __launch_bounds__(512, 1) void tc_gemm(
    const fp16* __restrict__ A,
    const fp16* __restrict__ Bh, const fp16* __restrict__ Bl,
    const float* __restrict__ bias,
    float* __restrict__ Cf, fp16* __restrict__ Ch,
    int N, int K, int relu, int outmode)
{
    extern __shared__ char smem[];
    const uint32_t sbase = smem_u32(smem);
    const int t = threadIdx.x, lane = t & 31;
    const int wid = t >> 5, wm = wid & 3, wn = wid >> 2;
    const int m0 = blockIdx.y * 128, n0 = blockIdx.x * 128;

    // loader mapping: 512 threads -> 128 rows x 4 16B-segments per array
    const int lrow = t >> 2, lseg = t & 3;
    const uint32_t sdst = (uint32_t)(lrow * LDB + lseg * 16);
    const size_t gaoff = (size_t)(m0 + lrow) * K + lseg * 8;
    const int bok = (n0 + lrow < N) ? 16 : 0;
    const size_t gboff = (size_t)(bok ? (n0 + lrow) : n0) * K + lseg * 8;

    float acc[2][4][4];
#pragma unroll
    for (int i = 0; i < 2; i++)
#pragma unroll
        for (int j = 0; j < 4; j++)
#pragma unroll
            for (int k = 0; k < 4; k++) acc[i][j][k] = 0.f;

    const int nc = K >> 5;

    // prologue: prefetch chunks 0,1
#pragma unroll
    for (int s = 0; s < 2; s++) {
        if (s < nc) {
            uint32_t sb = sbase + s * SSTG;
            size_t ka = (size_t)s * 32;
            cpa16(sb + sdst,            A  + gaoff + ka, 16);
            cpa16(sb + ASTG + sdst,     Bh + gboff + ka, bok);
            cpa16(sb + 2 * ASTG + sdst, Bl + gboff + ka, bok);
            cp_commit();
        }
    }

    // ldmatrix lane addressing (within-stage byte offsets)
    const uint32_t a_off = (uint32_t)((wm * 32 + (lane & 15)) * LDB
                                      + ((lane >> 4) << 3) * 2);
    const uint32_t b_off = (uint32_t)(ASTG
                                      + (wn * 32 + ((lane >> 4) << 3) + (lane & 7)) * LDB
                                      + (((lane >> 3) & 1) << 3) * 2);

    int slot = 0, nslot = 2;
    for (int c = 0; c < nc; c++) {
        if (c + 1 < nc) cp_wait1(); else cp_wait0();
        __syncthreads();
        if (c + 2 < nc) {
            uint32_t sb = sbase + nslot * SSTG;
            size_t ka = (size_t)(c + 2) * 32;
            cpa16(sb + sdst,            A  + gaoff + ka, 16);
            cpa16(sb + ASTG + sdst,     Bh + gboff + ka, bok);
            cpa16(sb + 2 * ASTG + sdst, Bl + gboff + ka, bok);
            cp_commit();
            nslot = nslot + 1 == NSTG ? 0 : nslot + 1;
        }

        const uint32_t sb = sbase + slot * SSTG;
        slot = slot + 1 == NSTG ? 0 : slot + 1;
#pragma unroll
        for (int ks = 0; ks < 2; ks++) {
            const uint32_t kb = ks * 32;
            uint32_t a[8], bh[8], bl[8];
            ldm4(a[0], a[1], a[2], a[3], sb + a_off + kb);
            ldm4(a[4], a[5], a[6], a[7], sb + a_off + kb + 16 * LDB);
            ldm4(bh[0], bh[1], bh[2], bh[3], sb + b_off + kb);
            ldm4(bh[4], bh[5], bh[6], bh[7], sb + b_off + kb + 16 * LDB);
            ldm4(bl[0], bl[1], bl[2], bl[3], sb + ASTG + b_off + kb);
            ldm4(bl[4], bl[5], bl[6], bl[7], sb + ASTG + b_off + kb + 16 * LDB);
#pragma unroll
            for (int mt = 0; mt < 2; mt++) {
#pragma unroll
                for (int nt = 0; nt < 4; nt++) {
                    mma16816(acc[mt][nt], a + mt * 4, bh + nt * 2);
                    mma16816(acc[mt][nt], a + mt * 4, bl + nt * 2);
                }
            }
        }
    }

    // epilogue
#pragma unroll
    for (int mt = 0; mt < 2; mt++) {
#pragma unroll
        for (int nt = 0; nt < 4; nt++) {
            int col = n0 + wn * 32 + nt * 8 + (lane & 3) * 2;
            if (col < N) {
                float2 bv = *(const float2*)(bias + col);
                int r0 = m0 + wm * 32 + mt * 16 + (lane >> 2);
                float v0 = acc[mt][nt][0] + bv.x;
                float v1 = acc[mt][nt][1] + bv.y;
                float v2 = acc[mt][nt][2] + bv.x;
                float v3 = acc[mt][nt][3] + bv.y;
                if (relu) {
                    v0 = fmaxf(v0, 0.f); v1 = fmaxf(v1, 0.f);
                    v2 = fmaxf(v2, 0.f); v3 = fmaxf(v3, 0.f);
                }
                if (outmode == 0) {
                    *(float2*)(Cf + (size_t)r0 * N + col)       = make_float2(v0, v1);
                    *(float2*)(Cf + (size_t)(r0 + 8) * N + col) = make_float2(v2, v3);
                } else {
                    size_t o0 = (size_t)r0 * N + col, o1 = (size_t)(r0 + 8) * N + col;
                    *(__half2*)(Ch + o0) = __floats2half2_rn(v0, v1);
                    *(__half2*)(Ch + o1) = __floats2half2_rn(v2, v3);
                }
            }
        }
    }
}

// ---------------- embed ----------------
__global__ void embed2_kernel(const int* __restrict__ inp,
                              const float* __restrict__ emb,
                              const float* __restrict__ pos,
                              float* __restrict__ xe, fp16* __restrict__ xh)
{
    int row = blockIdx.x, t = threadIdx.x;
    int tok = inp[row], tp = row % TT;
    float v = emb[(size_t)tok * HH + t] + pos[tp * HH + t];
    size_t o = (size_t)row * HH + t;
    xe[o] = v;
    xh[o] = __float2half_rn(v);
}

// ---------------- weight pack/convert ----------------
__global__ void conv_hilo(const float* __restrict__ x, fp16* __restrict__ h,
                          fp16* __restrict__ l, int n)
{
    int i = blockIdx.x * 256 + threadIdx.x;
    if (i < n) split_store_h(x[i], h, l, i);
}

__global__ void pack_wqkv(const float* q1, const float* k1, const float* v1,
                          const float* q2, const float* k2, const float* v2,
                          fp16* __restrict__ h, fp16* __restrict__ l)
{
    int r = blockIdx.x, c = threadIdx.x;   // 576 x 128
    int seg = r / 96, rr = r % 96;
    const float* src = seg == 0 ? q1 : seg == 1 ? k1 : seg == 2 ? v1
                     : seg == 3 ? q2 : seg == 4 ? k2 : v2;
    split_store_h(src[rr * 128 + c], h, l, (size_t)r * 128 + c);
}

// ---------------- attention ----------------
__global__ __launch_bounds__(256) void attn_kernel(
    const fp16* __restrict__ qkv, fp16* __restrict__ hcat)
{
    extern __shared__ float sm[];
    float* sq = sm;
    float* sk = sq + TT * DKK;
    float* sv = sk + TT * DKK;
    float* ss = sv + TT * DKK;

    const int t = threadIdx.x;
    const int n = blockIdx.x >> 1;
    const int hd = blockIdx.x & 1;
    const float scale = 0.10206207261596577f;

    const fp16* base = qkv + (size_t)n * TT * QKVC + hd * 288;
    for (int idx = t; idx < TT * DKK; idx += 256) {
        int i = idx / DKK, d = idx % DKK;
        const fp16* r = base + (size_t)i * QKVC;
        sq[idx] = __half2float(r[d]);
        sk[idx] = __half2float(r[96 + d]);
        sv[idx] = __half2float(r[192 + d]);
    }
    __syncthreads();
    for (int idx = t; idx < TT * TT; idx += 256) {
        int i = idx / TT, j = idx % TT;
        const float* qi = sq + i * DKK;
        const float* kj = sk + j * DKK;
        float a = 0.f;
#pragma unroll 8
        for (int d = 0; d < DKK; d++) a = fmaf(qi[d], kj[d], a);
        ss[idx] = a * scale;
    }
    __syncthreads();
    {
        int w = t >> 5, lane = t & 31;
        for (int i = w; i < TT; i += 8) {
            float* row = ss + i * TT;
            float m = -1e30f;
            for (int j = lane; j < TT; j += 32) m = fmaxf(m, row[j]);
#pragma unroll
            for (int o = 16; o; o >>= 1) m = fmaxf(m, __shfl_xor_sync(~0u, m, o));
            float s = 0.f;
            for (int j = lane; j < TT; j += 32) { float e = expf(row[j] - m); row[j] = e; s += e; }
#pragma unroll
            for (int o = 16; o; o >>= 1) s += __shfl_xor_sync(~0u, s, o);
            float inv = 1.f / s;
            for (int j = lane; j < TT; j += 32) row[j] *= inv;
        }
    }
    __syncthreads();
    for (int idx = t; idx < TT * DKK; idx += 256) {
        int i = idx / DKK, d = idx % DKK;
        const float* si = ss + i * TT;
        float a = 0.f;
#pragma unroll
        for (int j = 0; j < TT; j++) a = fmaf(si[j], sv[j * DKK + d], a);
        hcat[((size_t)(n * TT + i)) * 192 + hd * DKK + d] = __float2half_rn(a);
    }
}

// ---------------- add + LN ----------------
__global__ void add_ln2_kernel(const float* __restrict__ a,
                               const float* __restrict__ b,
                               const float* __restrict__ g,
                               const float* __restrict__ be,
                               float* __restrict__ outf, fp16* __restrict__ oh)
{
    int row = blockIdx.x, t = threadIdx.x;
    float v = a[(size_t)row * HH + t] + b[(size_t)row * HH + t];
    __shared__ float red[4];
    float s = v;
#pragma unroll
    for (int o = 16; o; o >>= 1) s += __shfl_xor_sync(~0u, s, o);
    if ((t & 31) == 0) red[t >> 5] = s;
    __syncthreads();
    float mean = (red[0] + red[1] + red[2] + red[3]) * (1.f / 128.f);
    __syncthreads();
    float d = v - mean, q = d * d;
#pragma unroll
    for (int o = 16; o; o >>= 1) q += __shfl_xor_sync(~0u, q, o);
    if ((t & 31) == 0) red[t >> 5] = q;
    __syncthreads();
    float var = (red[0] + red[1] + red[2] + red[3]) * (1.f / 128.f);
    float y = d * rsqrtf(var + 1e-5f) * g[t] + be[t];
    size_t o = (size_t)row * HH + t;
    if (outf) outf[o] = y;
    oh[o] = __float2half_rn(y);
}

// ---------------- launch ----------------
extern "C" void kernel_launch(void* const* d_in, const int* in_sizes, int n_in,
                              void* d_out, int out_size)
{
    const int*   inp   = (const int*)  d_in[0];
    const float* emb   = (const float*)d_in[1];
    const float* pos   = (const float*)d_in[2];
    const float* Wk1   = (const float*)d_in[3];
    const float* bk1   = (const float*)d_in[4];
    const float* Wv1   = (const float*)d_in[5];
    const float* bv1   = (const float*)d_in[6];
    const float* Wq1   = (const float*)d_in[7];
    const float* bq1   = (const float*)d_in[8];
    const float* Wk2   = (const float*)d_in[9];
    const float* bk2   = (const float*)d_in[10];
    const float* Wv2   = (const float*)d_in[11];
    const float* bv2   = (const float*)d_in[12];
    const float* Wq2   = (const float*)d_in[13];
    const float* bq2   = (const float*)d_in[14];
    const float* Wproj = (const float*)d_in[15];
    const float* bproj = (const float*)d_in[16];
    const float* g_mhp = (const float*)d_in[17];
    const float* b_mhp = (const float*)d_in[18];
    const float* Wff1  = (const float*)d_in[19];
    const float* bff1  = (const float*)d_in[20];
    const float* Wff2  = (const float*)d_in[21];
    const float* bff2  = (const float*)d_in[22];
    const float* g_ffp = (const float*)d_in[23];
    const float* b_ffp = (const float*)d_in[24];
    const float* Wfin  = (const float*)d_in[25];
    const float* bfin  = (const float*)d_in[26];
    float* out = (float*)d_out;

    float *xe, *bqkv, *mh, *x1, *ffo;
    fp16 *xeh, *wqh, *wql, *qkv, *hcat, *x1h, *ffh, *x2h;
    fp16 *wph, *wpl, *w1h, *w1l, *w2h, *w2l, *wfh, *wfl;
    cudaGetSymbolAddress((void**)&xe,  g_xe);
    cudaGetSymbolAddress((void**)&xeh, g_xeh);
    cudaGetSymbolAddress((void**)&wqh, g_wqkvh);
    cudaGetSymbolAddress((void**)&wql, g_wqkvl);
    cudaGetSymbolAddress((void**)&bqkv, g_bqkv);
    cudaGetSymbolAddress((void**)&qkv, g_qkv);
    cudaGetSymbolAddress((void**)&hcat, g_hcat);
    cudaGetSymbolAddress((void**)&mh,  g_mh);
    cudaGetSymbolAddress((void**)&x1,  g_x1);
    cudaGetSymbolAddress((void**)&x1h, g_x1h);
    cudaGetSymbolAddress((void**)&ffh, g_ffh);
    cudaGetSymbolAddress((void**)&ffo, g_ffo);
    cudaGetSymbolAddress((void**)&x2h, g_x2h);
    cudaGetSymbolAddress((void**)&wph, g_wprojh);
    cudaGetSymbolAddress((void**)&wpl, g_wprojl);
    cudaGetSymbolAddress((void**)&w1h, g_wff1h);
    cudaGetSymbolAddress((void**)&w1l, g_wff1l);
    cudaGetSymbolAddress((void**)&w2h, g_wff2h);
    cudaGetSymbolAddress((void**)&w2l, g_wff2l);
    cudaGetSymbolAddress((void**)&wfh, g_wfinh);
    cudaGetSymbolAddress((void**)&wfl, g_wfinl);

    const int GSM = NSTG * SSTG;   // 92160
    cudaFuncSetAttribute(tc_gemm, cudaFuncAttributeMaxDynamicSharedMemorySize, GSM);
    int asm_ = (3 * TT * DKK + TT * TT) * (int)sizeof(float);
    cudaFuncSetAttribute(attn_kernel, cudaFuncAttributeMaxDynamicSharedMemorySize, asm_);

    // 1) embed
    embed2_kernel<<<NT, 128>>>(inp, emb, pos, xe, xeh);

    // 2) weight packing / conversion
    pack_wqkv<<<QKVC, 128>>>(Wq1, Wk1, Wv1, Wq2, Wk2, Wv2, wqh, wql);
    const size_t bseg = (size_t)DKK * sizeof(float);
    cudaMemcpyAsync(bqkv + 0 * DKK, bq1, bseg, cudaMemcpyDeviceToDevice);
    cudaMemcpyAsync(bqkv + 1 * DKK, bk1, bseg, cudaMemcpyDeviceToDevice);
    cudaMemcpyAsync(bqkv + 2 * DKK, bv1, bseg, cudaMemcpyDeviceToDevice);
    cudaMemcpyAsync(bqkv + 3 * DKK, bq2, bseg, cudaMemcpyDeviceToDevice);
    cudaMemcpyAsync(bqkv + 4 * DKK, bk2, bseg, cudaMemcpyDeviceToDevice);
    cudaMemcpyAsync(bqkv + 5 * DKK, bv2, bseg, cudaMemcpyDeviceToDevice);
    conv_hilo<<<(HH * 192 + 255) / 256, 256>>>(Wproj, wph, wpl, HH * 192);
    conv_hilo<<<(DFF_ * HH + 255) / 256, 256>>>(Wff1, w1h, w1l, DFF_ * HH);
    conv_hilo<<<(HH * DFF_ + 255) / 256, 256>>>(Wff2, w2h, w2l, HH * DFF_);
    conv_hilo<<<(OUTV * HH + 255) / 256, 256>>>(Wfin, wfh, wfl, OUTV * HH);

    const int MB = NT / 128;  // 172

    // 3) QKV GEMM [NT,576] fp16 out, K=128
    tc_gemm<<<dim3((QKVC + 127) / 128, MB), 512, GSM>>>(
        xeh, wqh, wql, bqkv, nullptr, qkv, QKVC, HH, 0, 1);

    // 4) attention -> hcat fp16
    attn_kernel<<<NB * 2, 256, asm_>>>(qkv, hcat);

    // 5) proj GEMM [NT,128], K=192, fp32 out
    tc_gemm<<<dim3(1, MB), 512, GSM>>>(
        hcat, wph, wpl, bproj, mh, nullptr, HH, 192, 0, 0);

    // 6) x1 = LN(mh + xe): fp32 + fp16
    add_ln2_kernel<<<NT, 128>>>(mh, xe, g_mhp, b_mhp, x1, x1h);

    // 7) FFN1 + ReLU -> ffh fp16, K=128
    tc_gemm<<<dim3(DFF_ / 128, MB), 512, GSM>>>(
        x1h, w1h, w1l, bff1, nullptr, ffh, DFF_, HH, 1, 1);

    // 8) FFN2 [NT,128], K=2048, fp32 out
    tc_gemm<<<dim3(1, MB), 512, GSM>>>(
        ffh, w2h, w2l, bff2, ffo, nullptr, HH, DFF_, 0, 0);

    // 9) x2 = LN(ffo + x1): fp16 only (x1 reused as dummy fp32? -> pass nullptr)
    add_ln2_kernel<<<NT, 128>>>(ffo, x1, g_ffp, b_ffp, nullptr, x2h);

    // 10) final GEMM [NT,8000] -> d_out fp32, K=128
    tc_gemm<<<dim3((OUTV + 127) / 128, MB), 512, GSM>>>(
        x2h, wfh, wfl, bfin, out, nullptr, OUTV, HH, 0, 0);
}

// round 8
// speedup vs baseline: 3.5527x; 1.3477x over previous
#include <cuda_runtime.h>
#include <cuda_fp16.h>
#include <math.h>
#include <stdint.h>

// Problem constants
#define NB   512
#define TT   43
#define NT   (NB*TT)          // 22016 = 172*128
#define HH   128
#define DKK  96
#define DFF_ 2048
#define OUTV 8000
#define QKVC 576

typedef __half fp16;

// ---------------- scratch ----------------
__device__ float g_xe   [(size_t)NT * HH];
__device__ fp16  g_xeh  [(size_t)NT * HH];
__device__ fp16  g_wqkv [(size_t)QKVC * HH];
__device__ float g_bqkv [QKVC];
__device__ fp16  g_qkv  [(size_t)NT * QKVC];
__device__ fp16  g_hcat [(size_t)NT * 192];
__device__ float g_mh   [(size_t)NT * HH];
__device__ float g_x1   [(size_t)NT * HH];
__device__ fp16  g_x1h  [(size_t)NT * HH];
__device__ fp16  g_ffh  [(size_t)NT * DFF_];
__device__ float g_ffo  [(size_t)NT * HH];
__device__ fp16  g_x2h  [(size_t)NT * HH];
__device__ fp16  g_wproj[(size_t)HH * 192];
__device__ fp16  g_wff1 [(size_t)DFF_ * HH];
__device__ fp16  g_wff2 [(size_t)HH * DFF_];
__device__ fp16  g_wfin [(size_t)OUTV * HH];

// ---------------- helpers ----------------
__device__ __forceinline__ uint32_t smem_u32(const void* p) {
    uint32_t a;
    asm("{ .reg .u64 t; cvta.to.shared.u64 t, %1; cvt.u32.u64 %0, t; }"
        : "=r"(a) : "l"(p));
    return a;
}
__device__ __forceinline__ void cpa16(uint32_t dst, const void* src, int srcsize) {
    asm volatile("cp.async.ca.shared.global [%0], [%1], 16, %2;"
                 :: "r"(dst), "l"(src), "r"(srcsize) : "memory");
}
__device__ __forceinline__ void cp_commit() {
    asm volatile("cp.async.commit_group;" ::: "memory");
}
__device__ __forceinline__ void cp_wait0() {
    asm volatile("cp.async.wait_group 0;" ::: "memory");
}
__device__ __forceinline__ void cp_wait1() {
    asm volatile("cp.async.wait_group 1;" ::: "memory");
}
__device__ __forceinline__ void ldm4(uint32_t& r0, uint32_t& r1, uint32_t& r2,
                                     uint32_t& r3, uint32_t a) {
    asm volatile("ldmatrix.sync.aligned.m8n8.x4.shared.b16 {%0,%1,%2,%3}, [%4];"
                 : "=r"(r0), "=r"(r1), "=r"(r2), "=r"(r3) : "r"(a));
}
__device__ __forceinline__ void mma16816(float* d, const uint32_t* a,
                                         const uint32_t* b) {
    asm volatile(
        "mma.sync.aligned.m16n8k16.row.col.f32.f16.f16.f32 "
        "{%0,%1,%2,%3}, {%4,%5,%6,%7}, {%8,%9}, {%0,%1,%2,%3};"
        : "+f"(d[0]), "+f"(d[1]), "+f"(d[2]), "+f"(d[3])
        : "r"(a[0]), "r"(a[1]), "r"(a[2]), "r"(a[3]), "r"(b[0]), "r"(b[1]));
}

// ================= tensor-core GEMM (mma.sync fp16, single-pass) =============
// C[M,BNxblocks] = A[M,K](fp16) @ B[N,K]^T(fp16) + bias
// M-tile 128, N-tile BN (128 or 256), BK=32, 512 threads, 3-stage cp.async.
// SMEM/stage: A 128x80B + B BNx80B.
#define LDB  80
#define ASZ  10240           // A bytes per stage (128*80)
#define NSTG 3

template<int BN>
__global__ __launch_bounds__(512, 1) void tc_gemm(
    const fp16* __restrict__ A, const fp16* __restrict__ B,
    const float* __restrict__ bias,
    float* __restrict__ Cf, fp16* __restrict__ Ch,
    int N, int K, int relu, int outmode)
{
    constexpr int BSZ  = BN * LDB;       // B bytes per stage
    constexpr int SSTG = ASZ + BSZ;      // stage bytes
    constexpr int WNS  = BN / 4;         // warp n-span
    constexpr int NT_N = WNS / 8;        // n-subtiles per warp (4 or 8)
    constexpr int BIT  = BN / 128;       // B loader iterations

    extern __shared__ char smem[];
    const uint32_t sbase = smem_u32(smem);
    const int t = threadIdx.x, lane = t & 31;
    const int wid = t >> 5, wm = wid & 3, wn = wid >> 2;
    const int m0 = blockIdx.y * 128, n0 = blockIdx.x * BN;

    // loader mapping
    const int lrow = t >> 2, lseg = t & 3;
    const uint32_t sdstA = (uint32_t)(lrow * LDB + lseg * 16);
    const size_t gaoff = (size_t)(m0 + lrow) * K + lseg * 8;
    uint32_t sdstB[BIT];
    size_t   gboff[BIT];
    int      bok[BIT];
#pragma unroll
    for (int i = 0; i < BIT; i++) {
        int row = lrow + i * 128;
        bok[i] = (n0 + row < N) ? 16 : 0;
        sdstB[i] = (uint32_t)(ASZ + row * LDB + lseg * 16);
        gboff[i] = (size_t)(bok[i] ? (n0 + row) : n0) * K + lseg * 8;
    }

    float acc[2][NT_N][4];
#pragma unroll
    for (int i = 0; i < 2; i++)
#pragma unroll
        for (int j = 0; j < NT_N; j++)
#pragma unroll
            for (int k = 0; k < 4; k++) acc[i][j][k] = 0.f;

    const int nc = K >> 5;

    // prologue: prefetch chunks 0,1
#pragma unroll
    for (int s = 0; s < 2; s++) {
        if (s < nc) {
            uint32_t sb = sbase + s * SSTG;
            size_t ka = (size_t)s * 32;
            cpa16(sb + sdstA, A + gaoff + ka, 16);
#pragma unroll
            for (int i = 0; i < BIT; i++)
                cpa16(sb + sdstB[i], B + gboff[i] + ka, bok[i]);
            cp_commit();
        }
    }

    // ldmatrix lane addressing
    const uint32_t a_off = (uint32_t)((wm * 32 + (lane & 15)) * LDB
                                      + ((lane >> 4) << 3) * 2);
    const uint32_t b_off = (uint32_t)(ASZ
                                      + (wn * WNS + ((lane >> 4) << 3) + (lane & 7)) * LDB
                                      + (((lane >> 3) & 1) << 3) * 2);

    int slot = 0, nslot = 2;
    for (int c = 0; c < nc; c++) {
        if (c + 1 < nc) cp_wait1(); else cp_wait0();
        __syncthreads();
        if (c + 2 < nc) {
            uint32_t sb = sbase + nslot * SSTG;
            size_t ka = (size_t)(c + 2) * 32;
            cpa16(sb + sdstA, A + gaoff + ka, 16);
#pragma unroll
            for (int i = 0; i < BIT; i++)
                cpa16(sb + sdstB[i], B + gboff[i] + ka, bok[i]);
            cp_commit();
            nslot = nslot + 1 == NSTG ? 0 : nslot + 1;
        }

        const uint32_t sb = sbase + slot * SSTG;
        slot = slot + 1 == NSTG ? 0 : slot + 1;
#pragma unroll
        for (int ks = 0; ks < 2; ks++) {
            const uint32_t kb = ks * 32;
            uint32_t a[8], b[NT_N * 2];
            ldm4(a[0], a[1], a[2], a[3], sb + a_off + kb);
            ldm4(a[4], a[5], a[6], a[7], sb + a_off + kb + 16 * LDB);
#pragma unroll
            for (int g = 0; g < NT_N / 2; g++)
                ldm4(b[g * 4], b[g * 4 + 1], b[g * 4 + 2], b[g * 4 + 3],
                     sb + b_off + kb + g * 16 * LDB);
#pragma unroll
            for (int mt = 0; mt < 2; mt++)
#pragma unroll
                for (int nt = 0; nt < NT_N; nt++)
                    mma16816(acc[mt][nt], a + mt * 4, b + nt * 2);
        }
    }

    // epilogue
#pragma unroll
    for (int mt = 0; mt < 2; mt++) {
#pragma unroll
        for (int nt = 0; nt < NT_N; nt++) {
            int col = n0 + wn * WNS + nt * 8 + (lane & 3) * 2;
            if (col < N) {
                float2 bv = *(const float2*)(bias + col);
                int r0 = m0 + wm * 32 + mt * 16 + (lane >> 2);
                float v0 = acc[mt][nt][0] + bv.x;
                float v1 = acc[mt][nt][1] + bv.y;
                float v2 = acc[mt][nt][2] + bv.x;
                float v3 = acc[mt][nt][3] + bv.y;
                if (relu) {
                    v0 = fmaxf(v0, 0.f); v1 = fmaxf(v1, 0.f);
                    v2 = fmaxf(v2, 0.f); v3 = fmaxf(v3, 0.f);
                }
                if (outmode == 0) {
                    *(float2*)(Cf + (size_t)r0 * N + col)       = make_float2(v0, v1);
                    *(float2*)(Cf + (size_t)(r0 + 8) * N + col) = make_float2(v2, v3);
                } else {
                    size_t o0 = (size_t)r0 * N + col, o1 = (size_t)(r0 + 8) * N + col;
                    *(__half2*)(Ch + o0) = __floats2half2_rn(v0, v1);
                    *(__half2*)(Ch + o1) = __floats2half2_rn(v2, v3);
                }
            }
        }
    }
}

// ---------------- embed ----------------
__global__ void embed2_kernel(const int* __restrict__ inp,
                              const float* __restrict__ emb,
                              const float* __restrict__ pos,
                              float* __restrict__ xe, fp16* __restrict__ xh)
{
    int row = blockIdx.x, t = threadIdx.x;
    int tok = inp[row], tp = row % TT;
    float v = emb[(size_t)tok * HH + t] + pos[tp * HH + t];
    size_t o = (size_t)row * HH + t;
    xe[o] = v;
    xh[o] = __float2half_rn(v);
}

// ---------------- weight conversion ----------------
__global__ void conv_h(const float* __restrict__ x, fp16* __restrict__ h, int n)
{
    int i = blockIdx.x * 256 + threadIdx.x;
    if (i < n) h[i] = __float2half_rn(x[i]);
}

__global__ void pack_wqkv(const float* q1, const float* k1, const float* v1,
                          const float* q2, const float* k2, const float* v2,
                          fp16* __restrict__ h)
{
    int r = blockIdx.x, c = threadIdx.x;   // 576 x 128
    int seg = r / 96, rr = r % 96;
    const float* src = seg == 0 ? q1 : seg == 1 ? k1 : seg == 2 ? v1
                     : seg == 3 ? q2 : seg == 4 ? k2 : v2;
    h[(size_t)r * 128 + c] = __float2half_rn(src[rr * 128 + c]);
}

// ---------------- attention ----------------
__global__ __launch_bounds__(256) void attn_kernel(
    const fp16* __restrict__ qkv, fp16* __restrict__ hcat)
{
    extern __shared__ float sm[];
    float* sq = sm;
    float* sk = sq + TT * DKK;
    float* sv = sk + TT * DKK;
    float* ss = sv + TT * DKK;

    const int t = threadIdx.x;
    const int n = blockIdx.x >> 1;
    const int hd = blockIdx.x & 1;
    const float scale = 0.10206207261596577f;

    const fp16* base = qkv + (size_t)n * TT * QKVC + hd * 288;
    for (int idx = t; idx < TT * DKK; idx += 256) {
        int i = idx / DKK, d = idx % DKK;
        const fp16* r = base + (size_t)i * QKVC;
        sq[idx] = __half2float(r[d]);
        sk[idx] = __half2float(r[96 + d]);
        sv[idx] = __half2float(r[192 + d]);
    }
    __syncthreads();
    for (int idx = t; idx < TT * TT; idx += 256) {
        int i = idx / TT, j = idx % TT;
        const float* qi = sq + i * DKK;
        const float* kj = sk + j * DKK;
        float a = 0.f;
#pragma unroll 8
        for (int d = 0; d < DKK; d++) a = fmaf(qi[d], kj[d], a);
        ss[idx] = a * scale;
    }
    __syncthreads();
    {
        int w = t >> 5, lane = t & 31;
        for (int i = w; i < TT; i += 8) {
            float* row = ss + i * TT;
            float m = -1e30f;
            for (int j = lane; j < TT; j += 32) m = fmaxf(m, row[j]);
#pragma unroll
            for (int o = 16; o; o >>= 1) m = fmaxf(m, __shfl_xor_sync(~0u, m, o));
            float s = 0.f;
            for (int j = lane; j < TT; j += 32) { float e = expf(row[j] - m); row[j] = e; s += e; }
#pragma unroll
            for (int o = 16; o; o >>= 1) s += __shfl_xor_sync(~0u, s, o);
            float inv = 1.f / s;
            for (int j = lane; j < TT; j += 32) row[j] *= inv;
        }
    }
    __syncthreads();
    for (int idx = t; idx < TT * DKK; idx += 256) {
        int i = idx / DKK, d = idx % DKK;
        const float* si = ss + i * TT;
        float a = 0.f;
#pragma unroll
        for (int j = 0; j < TT; j++) a = fmaf(si[j], sv[j * DKK + d], a);
        hcat[((size_t)(n * TT + i)) * 192 + hd * DKK + d] = __float2half_rn(a);
    }
}

// ---------------- add + LN ----------------
__global__ void add_ln2_kernel(const float* __restrict__ a,
                               const float* __restrict__ b,
                               const float* __restrict__ g,
                               const float* __restrict__ be,
                               float* __restrict__ outf, fp16* __restrict__ oh)
{
    int row = blockIdx.x, t = threadIdx.x;
    float v = a[(size_t)row * HH + t] + b[(size_t)row * HH + t];
    __shared__ float red[4];
    float s = v;
#pragma unroll
    for (int o = 16; o; o >>= 1) s += __shfl_xor_sync(~0u, s, o);
    if ((t & 31) == 0) red[t >> 5] = s;
    __syncthreads();
    float mean = (red[0] + red[1] + red[2] + red[3]) * (1.f / 128.f);
    __syncthreads();
    float d = v - mean, q = d * d;
#pragma unroll
    for (int o = 16; o; o >>= 1) q += __shfl_xor_sync(~0u, q, o);
    if ((t & 31) == 0) red[t >> 5] = q;
    __syncthreads();
    float var = (red[0] + red[1] + red[2] + red[3]) * (1.f / 128.f);
    float y = d * rsqrtf(var + 1e-5f) * g[t] + be[t];
    size_t o = (size_t)row * HH + t;
    if (outf) outf[o] = y;
    oh[o] = __float2half_rn(y);
}

// ---------------- launch ----------------
extern "C" void kernel_launch(void* const* d_in, const int* in_sizes, int n_in,
                              void* d_out, int out_size)
{
    const int*   inp   = (const int*)  d_in[0];
    const float* emb   = (const float*)d_in[1];
    const float* pos   = (const float*)d_in[2];
    const float* Wk1   = (const float*)d_in[3];
    const float* bk1   = (const float*)d_in[4];
    const float* Wv1   = (const float*)d_in[5];
    const float* bv1   = (const float*)d_in[6];
    const float* Wq1   = (const float*)d_in[7];
    const float* bq1   = (const float*)d_in[8];
    const float* Wk2   = (const float*)d_in[9];
    const float* bk2   = (const float*)d_in[10];
    const float* Wv2   = (const float*)d_in[11];
    const float* bv2   = (const float*)d_in[12];
    const float* Wq2   = (const float*)d_in[13];
    const float* bq2   = (const float*)d_in[14];
    const float* Wproj = (const float*)d_in[15];
    const float* bproj = (const float*)d_in[16];
    const float* g_mhp = (const float*)d_in[17];
    const float* b_mhp = (const float*)d_in[18];
    const float* Wff1  = (const float*)d_in[19];
    const float* bff1  = (const float*)d_in[20];
    const float* Wff2  = (const float*)d_in[21];
    const float* bff2  = (const float*)d_in[22];
    const float* g_ffp = (const float*)d_in[23];
    const float* b_ffp = (const float*)d_in[24];
    const float* Wfin  = (const float*)d_in[25];
    const float* bfin  = (const float*)d_in[26];
    float* out = (float*)d_out;

    float *xe, *bqkv, *mh, *x1, *ffo;
    fp16 *xeh, *wq, *qkv, *hcat, *x1h, *ffh, *x2h, *wp, *w1, *w2, *wf;
    cudaGetSymbolAddress((void**)&xe,  g_xe);
    cudaGetSymbolAddress((void**)&xeh, g_xeh);
    cudaGetSymbolAddress((void**)&wq,  g_wqkv);
    cudaGetSymbolAddress((void**)&bqkv, g_bqkv);
    cudaGetSymbolAddress((void**)&qkv, g_qkv);
    cudaGetSymbolAddress((void**)&hcat, g_hcat);
    cudaGetSymbolAddress((void**)&mh,  g_mh);
    cudaGetSymbolAddress((void**)&x1,  g_x1);
    cudaGetSymbolAddress((void**)&x1h, g_x1h);
    cudaGetSymbolAddress((void**)&ffh, g_ffh);
    cudaGetSymbolAddress((void**)&ffo, g_ffo);
    cudaGetSymbolAddress((void**)&x2h, g_x2h);
    cudaGetSymbolAddress((void**)&wp,  g_wproj);
    cudaGetSymbolAddress((void**)&w1,  g_wff1);
    cudaGetSymbolAddress((void**)&w2,  g_wff2);
    cudaGetSymbolAddress((void**)&wf,  g_wfin);

    const int GSM128 = NSTG * (ASZ + 128 * LDB);   // 61440
    const int GSM256 = NSTG * (ASZ + 256 * LDB);   // 92160
    cudaFuncSetAttribute(tc_gemm<128>, cudaFuncAttributeMaxDynamicSharedMemorySize, GSM128);
    cudaFuncSetAttribute(tc_gemm<256>, cudaFuncAttributeMaxDynamicSharedMemorySize, GSM256);
    int asm_ = (3 * TT * DKK + TT * TT) * (int)sizeof(float);
    cudaFuncSetAttribute(attn_kernel, cudaFuncAttributeMaxDynamicSharedMemorySize, asm_);

    // 1) embed
    embed2_kernel<<<NT, 128>>>(inp, emb, pos, xe, xeh);

    // 2) weight conversion
    pack_wqkv<<<QKVC, 128>>>(Wq1, Wk1, Wv1, Wq2, Wk2, Wv2, wq);
    const size_t bseg = (size_t)DKK * sizeof(float);
    cudaMemcpyAsync(bqkv + 0 * DKK, bq1, bseg, cudaMemcpyDeviceToDevice);
    cudaMemcpyAsync(bqkv + 1 * DKK, bk1, bseg, cudaMemcpyDeviceToDevice);
    cudaMemcpyAsync(bqkv + 2 * DKK, bv1, bseg, cudaMemcpyDeviceToDevice);
    cudaMemcpyAsync(bqkv + 3 * DKK, bq2, bseg, cudaMemcpyDeviceToDevice);
    cudaMemcpyAsync(bqkv + 4 * DKK, bk2, bseg, cudaMemcpyDeviceToDevice);
    cudaMemcpyAsync(bqkv + 5 * DKK, bv2, bseg, cudaMemcpyDeviceToDevice);
    conv_h<<<(HH * 192 + 255) / 256, 256>>>(Wproj, wp, HH * 192);
    conv_h<<<(DFF_ * HH + 255) / 256, 256>>>(Wff1, w1, DFF_ * HH);
    conv_h<<<(HH * DFF_ + 255) / 256, 256>>>(Wff2, w2, HH * DFF_);
    conv_h<<<(OUTV * HH + 255) / 256, 256>>>(Wfin, wf, OUTV * HH);

    const int MB = NT / 128;  // 172

    // 3) QKV GEMM [NT,576] fp16 out, K=128
    tc_gemm<128><<<dim3((QKVC + 127) / 128, MB), 512, GSM128>>>(
        xeh, wq, bqkv, nullptr, qkv, QKVC, HH, 0, 1);

    // 4) attention -> hcat fp16
    attn_kernel<<<NB * 2, 256, asm_>>>(qkv, hcat);

    // 5) proj GEMM [NT,128], K=192, fp32 out
    tc_gemm<128><<<dim3(1, MB), 512, GSM128>>>(
        hcat, wp, bproj, mh, nullptr, HH, 192, 0, 0);

    // 6) x1 = LN(mh + xe)
    add_ln2_kernel<<<NT, 128>>>(mh, xe, g_mhp, b_mhp, x1, x1h);

    // 7) FFN1 + ReLU -> ffh fp16, K=128, N=2048 (wide tile)
    tc_gemm<256><<<dim3(DFF_ / 256, MB), 512, GSM256>>>(
        x1h, w1, bff1, nullptr, ffh, DFF_, HH, 1, 1);

    // 8) FFN2 [NT,128], K=2048, fp32 out
    tc_gemm<128><<<dim3(1, MB), 512, GSM128>>>(
        ffh, w2, bff2, ffo, nullptr, HH, DFF_, 0, 0);

    // 9) x2 = LN(ffo + x1)
    add_ln2_kernel<<<NT, 128>>>(ffo, x1, g_ffp, b_ffp, nullptr, x2h);

    // 10) final GEMM [NT,8000] -> d_out fp32, K=128 (wide tile)
    tc_gemm<256><<<dim3((OUTV + 255) / 256, MB), 512, GSM256>>>(
        x2h, wf, bfin, out, nullptr, OUTV, HH, 0, 0);
}

// round 9
// speedup vs baseline: 4.0596x; 1.1427x over previous
#include <cuda_runtime.h>
#include <cuda_fp16.h>
#include <math.h>
#include <stdint.h>

// Problem constants
#define NB   512
#define TT   43
#define NT   (NB*TT)          // 22016 = 172*128
#define HH   128
#define DKK  96
#define DFF_ 2048
#define OUTV 8000
#define QKVC 576

typedef __half fp16;

// ---------------- scratch ----------------
__device__ float g_xe   [(size_t)NT * HH];
__device__ fp16  g_xeh  [(size_t)NT * HH];
__device__ fp16  g_wqkv [(size_t)QKVC * HH];
__device__ float g_bqkv [QKVC];
__device__ fp16  g_qkv  [(size_t)NT * QKVC];
__device__ fp16  g_hcat [(size_t)NT * 192];
__device__ float g_x1   [(size_t)NT * HH];
__device__ fp16  g_x1h  [(size_t)NT * HH];
__device__ fp16  g_ffh  [(size_t)NT * DFF_];
__device__ fp16  g_x2h  [(size_t)NT * HH];
__device__ fp16  g_wproj[(size_t)HH * 192];
__device__ fp16  g_wff1 [(size_t)DFF_ * HH];
__device__ fp16  g_wff2 [(size_t)HH * DFF_];
__device__ fp16  g_wfin [(size_t)OUTV * HH];

// ---------------- helpers ----------------
__device__ __forceinline__ uint32_t smem_u32(const void* p) {
    uint32_t a;
    asm("{ .reg .u64 t; cvta.to.shared.u64 t, %1; cvt.u32.u64 %0, t; }"
        : "=r"(a) : "l"(p));
    return a;
}
__device__ __forceinline__ void cpa16(uint32_t dst, const void* src, int srcsize) {
    asm volatile("cp.async.ca.shared.global [%0], [%1], 16, %2;"
                 :: "r"(dst), "l"(src), "r"(srcsize) : "memory");
}
__device__ __forceinline__ void cp_commit() {
    asm volatile("cp.async.commit_group;" ::: "memory");
}
__device__ __forceinline__ void cp_wait0() {
    asm volatile("cp.async.wait_group 0;" ::: "memory");
}
__device__ __forceinline__ void ldm4(uint32_t& r0, uint32_t& r1, uint32_t& r2,
                                     uint32_t& r3, uint32_t a) {
    asm volatile("ldmatrix.sync.aligned.m8n8.x4.shared.b16 {%0,%1,%2,%3}, [%4];"
                 : "=r"(r0), "=r"(r1), "=r"(r2), "=r"(r3) : "r"(a));
}
__device__ __forceinline__ void mma16816(float* d, const uint32_t* a,
                                         const uint32_t* b) {
    asm volatile(
        "mma.sync.aligned.m16n8k16.row.col.f32.f16.f16.f32 "
        "{%0,%1,%2,%3}, {%4,%5,%6,%7}, {%8,%9}, {%0,%1,%2,%3};"
        : "+f"(d[0]), "+f"(d[1]), "+f"(d[2]), "+f"(d[3])
        : "r"(a[0]), "r"(a[1]), "r"(a[2]), "r"(a[3]), "r"(b[0]), "r"(b[1]));
}

// ================= tensor-core GEMM (mma.sync fp16) ==========================
// C[M,N] = A[M,K](fp16) @ B[N,K]^T(fp16) + bias
// M-tile 128, N-tile BN (128/256), BK=64, 512 threads, 2-stage double buffer.
// MODE 0: fp32 -> Cf;  1: fp16 -> Ch (opt relu);  2: fused add+LN (BN=128, N=128)
#define LDB  144             // 64 fp16 = 128B + 16B pad
#define ASZ  (128*LDB)       // 18432
#define LNP  132             // LN tile pitch (floats)

template<int BN, int MODE>
__global__ __launch_bounds__(512, 1) void tc_gemm(
    const fp16* __restrict__ A, const fp16* __restrict__ B,
    const float* __restrict__ bias,
    float* __restrict__ Cf, fp16* __restrict__ Ch,
    const float* __restrict__ Res, const float* __restrict__ gg,
    const float* __restrict__ bb,
    int N, int K, int relu)
{
    constexpr int BSZ  = BN * LDB;
    constexpr int SSTG = ASZ + BSZ;
    constexpr int WNS  = BN / 4;
    constexpr int NT_N = WNS / 8;        // 4 or 8
    constexpr int AIT  = 2;              // A loader iters (1024 tasks / 512)
    constexpr int BIT  = BN / 64;        // B loader iters

    extern __shared__ char smem[];
    const uint32_t sbase = smem_u32(smem);
    const int t = threadIdx.x, lane = t & 31;
    const int wid = t >> 5, wm = wid & 3, wn = wid >> 2;
    const int m0 = blockIdx.y * 128, n0 = blockIdx.x * BN;

    // loader tasks: 16B segments, 8 per row (BK=64 -> 128B)
    uint32_t sdstA[AIT]; size_t gaoff[AIT];
#pragma unroll
    for (int i = 0; i < AIT; i++) {
        int task = t + i * 512, row = task >> 3, seg = task & 7;
        sdstA[i] = (uint32_t)(row * LDB + seg * 16);
        gaoff[i] = (size_t)(m0 + row) * K + seg * 8;
    }
    uint32_t sdstB[BIT]; size_t gboff[BIT]; int bok[BIT];
#pragma unroll
    for (int i = 0; i < BIT; i++) {
        int task = t + i * 512, row = task >> 3, seg = task & 7;
        bok[i] = (n0 + row < N) ? 16 : 0;
        sdstB[i] = (uint32_t)(ASZ + row * LDB + seg * 16);
        gboff[i] = (size_t)(bok[i] ? (n0 + row) : n0) * K + seg * 8;
    }

    float acc[2][NT_N][4];
#pragma unroll
    for (int i = 0; i < 2; i++)
#pragma unroll
        for (int j = 0; j < NT_N; j++)
#pragma unroll
            for (int k = 0; k < 4; k++) acc[i][j][k] = 0.f;

    const int nc = K >> 6;

    // prologue: chunk 0 -> slot 0
    {
        uint32_t sb = sbase;
#pragma unroll
        for (int i = 0; i < AIT; i++) cpa16(sb + sdstA[i], A + gaoff[i], 16);
#pragma unroll
        for (int i = 0; i < BIT; i++) cpa16(sb + sdstB[i], B + gboff[i], bok[i]);
        cp_commit();
    }

    // ldmatrix lane addressing
    const uint32_t a_off = (uint32_t)((wm * 32 + (lane & 15)) * LDB
                                      + ((lane >> 4) << 3) * 2);
    const uint32_t b_off = (uint32_t)(ASZ
                                      + (wn * WNS + ((lane >> 4) << 3) + (lane & 7)) * LDB
                                      + (((lane >> 3) & 1) << 3) * 2);

    for (int c = 0; c < nc; c++) {
        cp_wait0();
        __syncthreads();
        if (c + 1 < nc) {
            uint32_t sb = sbase + ((c + 1) & 1) * SSTG;
            size_t ka = (size_t)(c + 1) * 64;
#pragma unroll
            for (int i = 0; i < AIT; i++) cpa16(sb + sdstA[i], A + gaoff[i] + ka, 16);
#pragma unroll
            for (int i = 0; i < BIT; i++) cpa16(sb + sdstB[i], B + gboff[i] + ka, bok[i]);
            cp_commit();
        }

        const uint32_t sb = sbase + (c & 1) * SSTG;
#pragma unroll
        for (int ks = 0; ks < 4; ks++) {
            const uint32_t kb = ks * 32;   // 16 fp16 = 32B
            uint32_t a[8], b[NT_N * 2];
            ldm4(a[0], a[1], a[2], a[3], sb + a_off + kb);
            ldm4(a[4], a[5], a[6], a[7], sb + a_off + kb + 16 * LDB);
#pragma unroll
            for (int g = 0; g < NT_N / 2; g++)
                ldm4(b[g * 4], b[g * 4 + 1], b[g * 4 + 2], b[g * 4 + 3],
                     sb + b_off + kb + g * 16 * LDB);
#pragma unroll
            for (int mt = 0; mt < 2; mt++)
#pragma unroll
                for (int nt = 0; nt < NT_N; nt++)
                    mma16816(acc[mt][nt], a + mt * 4, b + nt * 2);
        }
    }

    if (MODE == 2) {
        // fused bias + residual + LayerNorm (full-row tile: BN=128, N=128)
        __syncthreads();
        float* tile = (float*)smem;   // 128 x LNP
#pragma unroll
        for (int mt = 0; mt < 2; mt++) {
#pragma unroll
            for (int nt = 0; nt < NT_N; nt++) {
                int r = wm * 32 + mt * 16 + (lane >> 2);
                int c = wn * WNS + nt * 8 + (lane & 3) * 2;
                float2 bv = *(const float2*)(bias + c);
                tile[r * LNP + c]           = acc[mt][nt][0] + bv.x;
                tile[r * LNP + c + 1]       = acc[mt][nt][1] + bv.y;
                tile[(r + 8) * LNP + c]     = acc[mt][nt][2] + bv.x;
                tile[(r + 8) * LNP + c + 1] = acc[mt][nt][3] + bv.y;
            }
        }
        __syncthreads();
        const float4 gv = *(const float4*)(gg + lane * 4);
        const float4 bv = *(const float4*)(bb + lane * 4);
#pragma unroll
        for (int k = 0; k < 8; k++) {
            int row = wid * 8 + k;
            float4 v = *(float4*)(tile + row * LNP + lane * 4);
            float4 rs = *(const float4*)(Res + (size_t)(m0 + row) * HH + lane * 4);
            v.x += rs.x; v.y += rs.y; v.z += rs.z; v.w += rs.w;
            float s = v.x + v.y + v.z + v.w;
#pragma unroll
            for (int o = 16; o; o >>= 1) s += __shfl_xor_sync(~0u, s, o);
            float mean = s * (1.f / 128.f);
            float dx = v.x - mean, dy = v.y - mean, dz = v.z - mean, dw = v.w - mean;
            float q = dx * dx + dy * dy + dz * dz + dw * dw;
#pragma unroll
            for (int o = 16; o; o >>= 1) q += __shfl_xor_sync(~0u, q, o);
            float inv = rsqrtf(q * (1.f / 128.f) + 1e-5f);
            float y0 = dx * inv * gv.x + bv.x;
            float y1 = dy * inv * gv.y + bv.y;
            float y2 = dz * inv * gv.z + bv.z;
            float y3 = dw * inv * gv.w + bv.w;
            size_t o = (size_t)(m0 + row) * HH + lane * 4;
            if (Cf) *(float4*)(Cf + o) = make_float4(y0, y1, y2, y3);
            *(__half2*)(Ch + o)     = __floats2half2_rn(y0, y1);
            *(__half2*)(Ch + o + 2) = __floats2half2_rn(y2, y3);
        }
        return;
    }

    // MODE 0/1 epilogue
#pragma unroll
    for (int mt = 0; mt < 2; mt++) {
#pragma unroll
        for (int nt = 0; nt < NT_N; nt++) {
            int col = n0 + wn * WNS + nt * 8 + (lane & 3) * 2;
            if (col < N) {
                float2 bv = *(const float2*)(bias + col);
                int r0 = m0 + wm * 32 + mt * 16 + (lane >> 2);
                float v0 = acc[mt][nt][0] + bv.x;
                float v1 = acc[mt][nt][1] + bv.y;
                float v2 = acc[mt][nt][2] + bv.x;
                float v3 = acc[mt][nt][3] + bv.y;
                if (relu) {
                    v0 = fmaxf(v0, 0.f); v1 = fmaxf(v1, 0.f);
                    v2 = fmaxf(v2, 0.f); v3 = fmaxf(v3, 0.f);
                }
                if (MODE == 0) {
                    *(float2*)(Cf + (size_t)r0 * N + col)       = make_float2(v0, v1);
                    *(float2*)(Cf + (size_t)(r0 + 8) * N + col) = make_float2(v2, v3);
                } else {
                    size_t o0 = (size_t)r0 * N + col, o1 = (size_t)(r0 + 8) * N + col;
                    *(__half2*)(Ch + o0) = __floats2half2_rn(v0, v1);
                    *(__half2*)(Ch + o1) = __floats2half2_rn(v2, v3);
                }
            }
        }
    }
}

// ---------------- embed ----------------
__global__ void embed2_kernel(const int* __restrict__ inp,
                              const float* __restrict__ emb,
                              const float* __restrict__ pos,
                              float* __restrict__ xe, fp16* __restrict__ xh)
{
    int row = blockIdx.x, t = threadIdx.x;
    int tok = inp[row], tp = row % TT;
    float v = emb[(size_t)tok * HH + t] + pos[tp * HH + t];
    size_t o = (size_t)row * HH + t;
    xe[o] = v;
    xh[o] = __float2half_rn(v);
}

// ---------------- weight conversion (all four, one launch) ----------------
#define CS0 (HH*192)               // 24576
#define CS1 (CS0 + DFF_*HH)        // 286720
#define CS2 (CS1 + HH*DFF_)        // 548864
#define CS3 (CS2 + OUTV*HH)        // 1572864
__global__ void conv_all(const float* __restrict__ Wp, const float* __restrict__ W1,
                         const float* __restrict__ W2, const float* __restrict__ Wf,
                         fp16* __restrict__ wp, fp16* __restrict__ w1,
                         fp16* __restrict__ w2, fp16* __restrict__ wf)
{
    int i = blockIdx.x * 256 + threadIdx.x;
    if (i < CS0)      wp[i]       = __float2half_rn(Wp[i]);
    else if (i < CS1) w1[i - CS0] = __float2half_rn(W1[i - CS0]);
    else if (i < CS2) w2[i - CS1] = __float2half_rn(W2[i - CS1]);
    else if (i < CS3) wf[i - CS2] = __float2half_rn(Wf[i - CS2]);
}

__global__ void pack_wqkv(const float* q1, const float* k1, const float* v1,
                          const float* q2, const float* k2, const float* v2,
                          fp16* __restrict__ h)
{
    int r = blockIdx.x, c = threadIdx.x;   // 576 x 128
    int seg = r / 96, rr = r % 96;
    const float* src = seg == 0 ? q1 : seg == 1 ? k1 : seg == 2 ? v1
                     : seg == 3 ? q2 : seg == 4 ? k2 : v2;
    h[(size_t)r * 128 + c] = __float2half_rn(src[rr * 128 + c]);
}

__global__ void pack_bias(const float* q1, const float* k1, const float* v1,
                          const float* q2, const float* k2, const float* v2,
                          float* __restrict__ b)
{
    int t = threadIdx.x;                   // 576
    int seg = t / 96, rr = t % 96;
    const float* src = seg == 0 ? q1 : seg == 1 ? k1 : seg == 2 ? v1
                     : seg == 3 ? q2 : seg == 4 ? k2 : v2;
    b[t] = src[rr];
}

// ---------------- attention ----------------
__global__ __launch_bounds__(256) void attn_kernel(
    const fp16* __restrict__ qkv, fp16* __restrict__ hcat)
{
    extern __shared__ float sm[];
    float* sq = sm;
    float* sk = sq + TT * DKK;
    float* sv = sk + TT * DKK;
    float* ss = sv + TT * DKK;

    const int t = threadIdx.x;
    const int n = blockIdx.x >> 1;
    const int hd = blockIdx.x & 1;
    const float scale = 0.10206207261596577f;

    const fp16* base = qkv + (size_t)n * TT * QKVC + hd * 288;
    for (int idx = t; idx < TT * DKK; idx += 256) {
        int i = idx / DKK, d = idx % DKK;
        const fp16* r = base + (size_t)i * QKVC;
        sq[idx] = __half2float(r[d]) * scale;   // pre-scale q
        sk[idx] = __half2float(r[96 + d]);
        sv[idx] = __half2float(r[192 + d]);
    }
    __syncthreads();
    for (int idx = t; idx < TT * TT; idx += 256) {
        int i = idx / TT, j = idx % TT;
        const float* qi = sq + i * DKK;
        const float* kj = sk + j * DKK;
        float a = 0.f;
#pragma unroll 8
        for (int d = 0; d < DKK; d++) a = fmaf(qi[d], kj[d], a);
        ss[idx] = a;
    }
    __syncthreads();
    {
        int w = t >> 5, lane = t & 31;
        for (int i = w; i < TT; i += 8) {
            float* row = ss + i * TT;
            float m = -1e30f;
            for (int j = lane; j < TT; j += 32) m = fmaxf(m, row[j]);
#pragma unroll
            for (int o = 16; o; o >>= 1) m = fmaxf(m, __shfl_xor_sync(~0u, m, o));
            float s = 0.f;
            for (int j = lane; j < TT; j += 32) { float e = expf(row[j] - m); row[j] = e; s += e; }
#pragma unroll
            for (int o = 16; o; o >>= 1) s += __shfl_xor_sync(~0u, s, o);
            float inv = 1.f / s;
            for (int j = lane; j < TT; j += 32) row[j] *= inv;
        }
    }
    __syncthreads();
    for (int idx = t; idx < TT * DKK; idx += 256) {
        int i = idx / DKK, d = idx % DKK;
        const float* si = ss + i * TT;
        float a = 0.f;
#pragma unroll
        for (int j = 0; j < TT; j++) a = fmaf(si[j], sv[j * DKK + d], a);
        hcat[((size_t)(n * TT + i)) * 192 + hd * DKK + d] = __float2half_rn(a);
    }
}

// ---------------- launch ----------------
extern "C" void kernel_launch(void* const* d_in, const int* in_sizes, int n_in,
                              void* d_out, int out_size)
{
    const int*   inp   = (const int*)  d_in[0];
    const float* emb   = (const float*)d_in[1];
    const float* pos   = (const float*)d_in[2];
    const float* Wk1   = (const float*)d_in[3];
    const float* bk1   = (const float*)d_in[4];
    const float* Wv1   = (const float*)d_in[5];
    const float* bv1   = (const float*)d_in[6];
    const float* Wq1   = (const float*)d_in[7];
    const float* bq1   = (const float*)d_in[8];
    const float* Wk2   = (const float*)d_in[9];
    const float* bk2   = (const float*)d_in[10];
    const float* Wv2   = (const float*)d_in[11];
    const float* bv2   = (const float*)d_in[12];
    const float* Wq2   = (const float*)d_in[13];
    const float* bq2   = (const float*)d_in[14];
    const float* Wproj = (const float*)d_in[15];
    const float* bproj = (const float*)d_in[16];
    const float* g_mhp = (const float*)d_in[17];
    const float* b_mhp = (const float*)d_in[18];
    const float* Wff1  = (const float*)d_in[19];
    const float* bff1  = (const float*)d_in[20];
    const float* Wff2  = (const float*)d_in[21];
    const float* bff2  = (const float*)d_in[22];
    const float* g_ffp = (const float*)d_in[23];
    const float* b_ffp = (const float*)d_in[24];
    const float* Wfin  = (const float*)d_in[25];
    const float* bfin  = (const float*)d_in[26];
    float* out = (float*)d_out;

    float *xe, *bqkv, *x1;
    fp16 *xeh, *wq, *qkv, *hcat, *x1h, *ffh, *x2h, *wp, *w1, *w2, *wf;
    cudaGetSymbolAddress((void**)&xe,  g_xe);
    cudaGetSymbolAddress((void**)&xeh, g_xeh);
    cudaGetSymbolAddress((void**)&wq,  g_wqkv);
    cudaGetSymbolAddress((void**)&bqkv, g_bqkv);
    cudaGetSymbolAddress((void**)&qkv, g_qkv);
    cudaGetSymbolAddress((void**)&hcat, g_hcat);
    cudaGetSymbolAddress((void**)&x1,  g_x1);
    cudaGetSymbolAddress((void**)&x1h, g_x1h);
    cudaGetSymbolAddress((void**)&ffh, g_ffh);
    cudaGetSymbolAddress((void**)&x2h, g_x2h);
    cudaGetSymbolAddress((void**)&wp,  g_wproj);
    cudaGetSymbolAddress((void**)&w1,  g_wff1);
    cudaGetSymbolAddress((void**)&w2,  g_wff2);
    cudaGetSymbolAddress((void**)&wf,  g_wfin);

    const int GSM128 = 2 * (ASZ + 128 * LDB);   // 73728
    const int GSM256 = 2 * (ASZ + 256 * LDB);   // 110592
    cudaFuncSetAttribute(tc_gemm<128,0>, cudaFuncAttributeMaxDynamicSharedMemorySize, GSM128);
    cudaFuncSetAttribute(tc_gemm<128,1>, cudaFuncAttributeMaxDynamicSharedMemorySize, GSM128);
    cudaFuncSetAttribute(tc_gemm<128,2>, cudaFuncAttributeMaxDynamicSharedMemorySize, GSM128);
    cudaFuncSetAttribute(tc_gemm<256,0>, cudaFuncAttributeMaxDynamicSharedMemorySize, GSM256);
    cudaFuncSetAttribute(tc_gemm<256,1>, cudaFuncAttributeMaxDynamicSharedMemorySize, GSM256);
    int asm_ = (3 * TT * DKK + TT * TT) * (int)sizeof(float);
    cudaFuncSetAttribute(attn_kernel, cudaFuncAttributeMaxDynamicSharedMemorySize, asm_);

    // 1) embed
    embed2_kernel<<<NT, 128>>>(inp, emb, pos, xe, xeh);

    // 2) weight conversion (3 launches total)
    pack_wqkv<<<QKVC, 128>>>(Wq1, Wk1, Wv1, Wq2, Wk2, Wv2, wq);
    pack_bias<<<1, QKVC>>>(bq1, bk1, bv1, bq2, bk2, bv2, bqkv);
    conv_all<<<CS3 / 256, 256>>>(Wproj, Wff1, Wff2, Wfin, wp, w1, w2, wf);

    const int MB = NT / 128;  // 172

    // 3) QKV GEMM [NT,576] fp16 out, K=128
    tc_gemm<128,1><<<dim3((QKVC + 127) / 128, MB), 512, GSM128>>>(
        xeh, wq, bqkv, nullptr, qkv, nullptr, nullptr, nullptr, QKVC, HH, 0);

    // 4) attention -> hcat fp16
    attn_kernel<<<NB * 2, 256, asm_>>>(qkv, hcat);

    // 5) proj GEMM + add + LN fused: x1 = LN(hcat@Wp + bproj + xe)
    tc_gemm<128,2><<<dim3(1, MB), 512, GSM128>>>(
        hcat, wp, bproj, x1, x1h, xe, g_mhp, b_mhp, HH, 192, 0);

    // 6) FFN1 + ReLU -> ffh fp16, K=128, N=2048 (wide tile)
    tc_gemm<256,1><<<dim3(DFF_ / 256, MB), 512, GSM256>>>(
        x1h, w1, bff1, nullptr, ffh, nullptr, nullptr, nullptr, DFF_, HH, 1);

    // 7) FFN2 + add + LN fused: x2h = LN(ffh@W2 + bff2 + x1), K=2048
    tc_gemm<128,2><<<dim3(1, MB), 512, GSM128>>>(
        ffh, w2, bff2, nullptr, x2h, x1, g_ffp, b_ffp, HH, DFF_, 0);

    // 8) final GEMM [NT,8000] -> d_out fp32, K=128 (wide tile)
    tc_gemm<256,0><<<dim3((OUTV + 255) / 256, MB), 512, GSM256>>>(
        x2h, wf, bfin, out, nullptr, nullptr, nullptr, nullptr, OUTV, HH, 0);
}